// round 11
// baseline (speedup 1.0000x reference)
#include <cuda_runtime.h>
#include <math.h>
#include <stdint.h>

#define HN   16
#define KVN  8
#define HDIM 64
#define WIN  512
#define BATCH 2
#define SEQ  2048
#define DM   1024

// Scratch — layouts:
// g_q: [B, HN, S, 64] (pre-RoPE), g_k/g_v: [B, KVN, S, 64] (pre-RoPE),
// g_attn: [B*S, HN*64]
__device__ float g_q[(size_t)BATCH * HN * SEQ * HDIM];
__device__ float g_k[(size_t)BATCH * KVN * SEQ * HDIM];
__device__ float g_v[(size_t)BATCH * KVN * SEQ * HDIM];
__device__ float g_attn[(size_t)BATCH * SEQ * HN * HDIM];
// RoPE tables: [SEQ][32]
__device__ float g_cos[SEQ * 32];
__device__ float g_sin[SEQ * 32];

// ---------------------------------------------------------------------------
// RoPE table, double-precision trig (immune to --use_fast_math).
// ---------------------------------------------------------------------------
__global__ void build_rope_table()
{
    const int idx = blockIdx.x * blockDim.x + threadIdx.x;
    if (idx >= SEQ * 32) return;
    const int p = idx & 31;
    const int s = idx >> 5;
    const double invf = pow(10000.0, -((double)(2 * p)) / 64.0);
    const double ang = (double)s * invf;
    g_cos[idx] = (float)cos(ang);
    g_sin[idx] = (float)sin(ang);
}

// ---------------------------------------------------------------------------
// tf32 helpers (validated R8/R9)
// ---------------------------------------------------------------------------
__device__ __forceinline__ uint32_t f2tf32(float f) {
    uint32_t u;
    asm("cvt.rna.tf32.f32 %0, %1;" : "=r"(u) : "f"(f));
    return u;
}

__device__ __forceinline__ void mma16n8k8(float* d, const uint32_t* a,
                                          const uint32_t* b) {
    asm("mma.sync.aligned.m16n8k8.row.col.f32.tf32.tf32.f32 "
        "{%0,%1,%2,%3}, {%4,%5,%6,%7}, {%8,%9}, {%0,%1,%2,%3};"
        : "+f"(d[0]), "+f"(d[1]), "+f"(d[2]), "+f"(d[3])
        : "r"(a[0]), "r"(a[1]), "r"(a[2]), "r"(a[3]),
          "r"(b[0]), "r"(b[1]));
}

#define CP_ASYNC16(dst_u32, src_ptr) \
    asm volatile("cp.async.ca.shared.global [%0], [%1], 16;" \
                 :: "r"(dst_u32), "l"(src_ptr))
#define CP_COMMIT() asm volatile("cp.async.commit_group;")
#define CP_WAIT(n)  asm volatile("cp.async.wait_group %0;" :: "n"(n))

// ---------------------------------------------------------------------------
// cp.async double-buffered tf32 GEMM body (validated R10). C = A[M,K]@B[K,N].
// BM=BN=128, BK=16, 256 threads, warp tile 64x32. fp32 in smem, cvt at load.
// ---------------------------------------------------------------------------
template <int MODE>
__device__ __forceinline__ void gemm_body(
    const float* __restrict__ A, const float* __restrict__ Bm,
    float* __restrict__ C, int M, int N, int K, int NH)
{
    __shared__ float As[2][128][20];
    __shared__ float Bs[2][16][136];

    const int tid  = threadIdx.x;
    const int lane = tid & 31;
    const int wid  = tid >> 5;
    const int wy   = wid >> 2;
    const int wx   = wid & 3;
    const int r4   = lane >> 2;
    const int c4   = lane & 3;
    const int m0   = blockIdx.y * 128, n0 = blockIdx.x * 128;

    const int NT = K / 16;

    {
#pragma unroll
        for (int i0 = 0; i0 < 2; i0++) {
            const int i = tid + i0 * 256;
            const int r = i >> 2, c = (i & 3) * 4;
            CP_ASYNC16((uint32_t)__cvta_generic_to_shared(&As[0][r][c]),
                       A + (size_t)(m0 + r) * K + c);
            const int br = i >> 5, bc = (i & 31) * 4;
            CP_ASYNC16((uint32_t)__cvta_generic_to_shared(&Bs[0][br][bc]),
                       Bm + (size_t)br * N + n0 + bc);
        }
        CP_COMMIT();
    }

    float acc[4][4][4] = {};
    int buf = 0;

    for (int kt = 0; kt < NT; kt++) {
        if (kt + 1 < NT) {
            const int k0 = (kt + 1) * 16;
            const int nb = buf ^ 1;
#pragma unroll
            for (int i0 = 0; i0 < 2; i0++) {
                const int i = tid + i0 * 256;
                const int r = i >> 2, c = (i & 3) * 4;
                CP_ASYNC16((uint32_t)__cvta_generic_to_shared(&As[nb][r][c]),
                           A + (size_t)(m0 + r) * K + k0 + c);
                const int br = i >> 5, bc = (i & 31) * 4;
                CP_ASYNC16((uint32_t)__cvta_generic_to_shared(&Bs[nb][br][bc]),
                           Bm + (size_t)(k0 + br) * N + n0 + bc);
            }
            CP_COMMIT();
            CP_WAIT(1);
        } else {
            CP_WAIT(0);
        }
        __syncthreads();

#pragma unroll
        for (int kk = 0; kk < 16; kk += 8) {
            uint32_t af[4][4], bf[4][2];
#pragma unroll
            for (int mt = 0; mt < 4; mt++) {
                const int mb = wy * 64 + mt * 16;
                af[mt][0] = f2tf32(As[buf][mb + r4    ][kk + c4    ]);
                af[mt][1] = f2tf32(As[buf][mb + r4 + 8][kk + c4    ]);
                af[mt][2] = f2tf32(As[buf][mb + r4    ][kk + c4 + 4]);
                af[mt][3] = f2tf32(As[buf][mb + r4 + 8][kk + c4 + 4]);
            }
#pragma unroll
            for (int nt = 0; nt < 4; nt++) {
                const int nb2 = wx * 32 + nt * 8;
                bf[nt][0] = f2tf32(Bs[buf][kk + c4    ][nb2 + r4]);
                bf[nt][1] = f2tf32(Bs[buf][kk + c4 + 4][nb2 + r4]);
            }
#pragma unroll
            for (int mt = 0; mt < 4; mt++)
#pragma unroll
                for (int nt = 0; nt < 4; nt++)
                    mma16n8k8(acc[mt][nt], af[mt], bf[nt]);
        }
        __syncthreads();
        buf ^= 1;
    }

#pragma unroll
    for (int mt = 0; mt < 4; mt++) {
#pragma unroll
        for (int nt = 0; nt < 4; nt++) {
            const int m = m0 + wy * 64 + mt * 16 + r4;
            const int n = n0 + wx * 32 + nt * 8 + 2 * c4;
#pragma unroll
            for (int half = 0; half < 2; half++) {
                const int mr = m + half * 8;
                float2 o = make_float2(acc[mt][nt][half * 2],
                                       acc[mt][nt][half * 2 + 1]);
                if (MODE == 0) {
                    *(float2*)(C + (size_t)mr * N + n) = o;
                } else {
                    const int b = mr / SEQ, s = mr % SEQ;
                    const int h = n >> 6, d = n & 63;
                    *(float2*)(C + (((size_t)(b * NH + h)) * SEQ + s) * HDIM + d) = o;
                }
            }
        }
    }
}

__global__ void __launch_bounds__(256, 2)
gemm_qkv(const float* __restrict__ hs,
         const float* __restrict__ Wq, const float* __restrict__ Wk,
         const float* __restrict__ Wv,
         float* __restrict__ qp, float* __restrict__ kp, float* __restrict__ vp)
{
    const int z = blockIdx.z;
    const float* Bm; float* C; int N, NH;
    if (z == 0)      { Bm = Wq; C = qp; N = HN  * HDIM; NH = HN;  }
    else if (z == 1) { Bm = Wk; C = kp; N = KVN * HDIM; NH = KVN; }
    else             { Bm = Wv; C = vp; N = KVN * HDIM; NH = KVN; }
    if (blockIdx.x * 128 >= N) return;
    gemm_body<1>(hs, Bm, C, BATCH * SEQ, N, DM, NH);
}

__global__ void __launch_bounds__(256, 2)
gemm_out(const float* __restrict__ A, const float* __restrict__ Bm,
         float* __restrict__ C)
{
    gemm_body<0>(A, Bm, C, BATCH * SEQ, DM, DM, 0);
}

// ---------------------------------------------------------------------------
// MMA flash attention v2: 256 threads = 8 warps = one 128-query tile
// (each warp owns 16 rows). RoPE fused into Q/K staging (from table).
// Arbitrary-mask safety: p zeroed by predicate (sacc > -1e29).
// Smem: Ps[128][72] (Q stage/P), Ks[64][72], Vs[64][72] = 72 KB dynamic.
// ---------------------------------------------------------------------------
#define ATS 72
#define ATTN_SMEM_BYTES ((128 + 64 + 64) * ATS * 4)

__global__ void __launch_bounds__(256) attn_mma()
{
    extern __shared__ uint32_t smu[];
    uint32_t (*Ps)[ATS] = (uint32_t(*)[ATS])(smu);
    uint32_t (*Ks)[ATS] = (uint32_t(*)[ATS])(smu + 128 * ATS);
    uint32_t (*Vs)[ATS] = (uint32_t(*)[ATS])(smu + (128 + 64) * ATS);

    const int b = blockIdx.z, h = blockIdx.y;
    const int qb = blockIdx.x * 128;
    const int kvh = h >> 1;            // n_rep = 2
    const int tid  = threadIdx.x;
    const int lane = tid & 31;
    const int wid  = tid >> 5;         // 0..7
    const int mb   = wid * 16;
    const int r4   = lane >> 2;
    const int c4   = lane & 3;

    const float* qg = g_q + ((size_t)(b * HN + h) * SEQ + qb) * HDIM;
    const float* kg = g_k + (size_t)(b * KVN + kvh) * SEQ * HDIM;
    const float* vg = g_v + (size_t)(b * KVN + kvh) * SEQ * HDIM;

    // Stage Q with fused RoPE + 0.125 scale. i indexes 128 rows x 8 f4 (cols<32).
    for (int i = tid; i < 128 * 8; i += 256) {
        const int row = i >> 3;
        const int col = (i & 7) * 4;
        const float4 x1 = *(const float4*)(qg + row * HDIM + col);
        const float4 x2 = *(const float4*)(qg + row * HDIM + col + 32);
        const float4 cc = *(const float4*)(&g_cos[(qb + row) * 32 + col]);
        const float4 ss = *(const float4*)(&g_sin[(qb + row) * 32 + col]);
        Ps[row][col + 0]  = f2tf32((x1.x * cc.x - x2.x * ss.x) * 0.125f);
        Ps[row][col + 1]  = f2tf32((x1.y * cc.y - x2.y * ss.y) * 0.125f);
        Ps[row][col + 2]  = f2tf32((x1.z * cc.z - x2.z * ss.z) * 0.125f);
        Ps[row][col + 3]  = f2tf32((x1.w * cc.w - x2.w * ss.w) * 0.125f);
        Ps[row][col + 32] = f2tf32((x2.x * cc.x + x1.x * ss.x) * 0.125f);
        Ps[row][col + 33] = f2tf32((x2.y * cc.y + x1.y * ss.y) * 0.125f);
        Ps[row][col + 34] = f2tf32((x2.z * cc.z + x1.z * ss.z) * 0.125f);
        Ps[row][col + 35] = f2tf32((x2.w * cc.w + x1.w * ss.w) * 0.125f);
    }
    __syncthreads();

    uint32_t aq[8][4];
#pragma unroll
    for (int ks = 0; ks < 8; ks++) {
        aq[ks][0] = Ps[mb + r4    ][ks * 8 + c4    ];
        aq[ks][1] = Ps[mb + r4 + 8][ks * 8 + c4    ];
        aq[ks][2] = Ps[mb + r4    ][ks * 8 + c4 + 4];
        aq[ks][3] = Ps[mb + r4 + 8][ks * 8 + c4 + 4];
    }

    float oacc[8][4] = {};
    float m2[2] = {-1e30f, -1e30f};
    float l2[2] = {0.0f, 0.0f};
    const int qi0 = qb + mb + r4;
    const int qi1 = qi0 + 8;

    const int kstart = (qb >= WIN) ? (qb - WIN) : 0;
    const int kend   = qb + 64;        // tile containing qb+127

    for (int kb = kstart; kb <= kend; kb += 64) {
        __syncthreads();
        // K staging with fused RoPE (row kb+row), V staging plain.
        for (int i = tid; i < 64 * 8; i += 256) {
            const int row = i >> 3;
            const int col = (i & 7) * 4;
            const float4 x1 = *(const float4*)(kg + (size_t)(kb + row) * HDIM + col);
            const float4 x2 = *(const float4*)(kg + (size_t)(kb + row) * HDIM + col + 32);
            const float4 cc = *(const float4*)(&g_cos[(kb + row) * 32 + col]);
            const float4 ss = *(const float4*)(&g_sin[(kb + row) * 32 + col]);
            Ks[row][col + 0]  = f2tf32(x1.x * cc.x - x2.x * ss.x);
            Ks[row][col + 1]  = f2tf32(x1.y * cc.y - x2.y * ss.y);
            Ks[row][col + 2]  = f2tf32(x1.z * cc.z - x2.z * ss.z);
            Ks[row][col + 3]  = f2tf32(x1.w * cc.w - x2.w * ss.w);
            Ks[row][col + 32] = f2tf32(x2.x * cc.x + x1.x * ss.x);
            Ks[row][col + 33] = f2tf32(x2.y * cc.y + x1.y * ss.y);
            Ks[row][col + 34] = f2tf32(x2.z * cc.z + x1.z * ss.z);
            Ks[row][col + 35] = f2tf32(x2.w * cc.w + x1.w * ss.w);
        }
        for (int i = tid; i < 64 * 16; i += 256) {
            const int f = i * 4;
            const int row = f >> 6, col = f & 63;
            float4 vv = *(const float4*)(vg + (size_t)kb * HDIM + f);
            Vs[row][col + 0] = f2tf32(vv.x); Vs[row][col + 1] = f2tf32(vv.y);
            Vs[row][col + 2] = f2tf32(vv.z); Vs[row][col + 3] = f2tf32(vv.w);
        }
        __syncthreads();

        float sacc[8][4] = {};
#pragma unroll
        for (int ks = 0; ks < 8; ks++) {
#pragma unroll
            for (int nt = 0; nt < 8; nt++) {
                uint32_t bk[2];
                bk[0] = Ks[nt * 8 + r4][ks * 8 + c4    ];
                bk[1] = Ks[nt * 8 + r4][ks * 8 + c4 + 4];
                mma16n8k8(sacc[nt], aq[ks], bk);
            }
        }

        float rmax0 = -1e30f, rmax1 = -1e30f;
#pragma unroll
        for (int nt = 0; nt < 8; nt++) {
            const int kj = kb + nt * 8 + 2 * c4;
            if (!((kj     <= qi0) && (kj     + WIN >= qi0))) sacc[nt][0] = -1e30f;
            if (!((kj + 1 <= qi0) && (kj + 1 + WIN >= qi0))) sacc[nt][1] = -1e30f;
            if (!((kj     <= qi1) && (kj     + WIN >= qi1))) sacc[nt][2] = -1e30f;
            if (!((kj + 1 <= qi1) && (kj + 1 + WIN >= qi1))) sacc[nt][3] = -1e30f;
            rmax0 = fmaxf(rmax0, fmaxf(sacc[nt][0], sacc[nt][1]));
            rmax1 = fmaxf(rmax1, fmaxf(sacc[nt][2], sacc[nt][3]));
        }
        rmax0 = fmaxf(rmax0, __shfl_xor_sync(0xffffffffu, rmax0, 1));
        rmax0 = fmaxf(rmax0, __shfl_xor_sync(0xffffffffu, rmax0, 2));
        rmax1 = fmaxf(rmax1, __shfl_xor_sync(0xffffffffu, rmax1, 1));
        rmax1 = fmaxf(rmax1, __shfl_xor_sync(0xffffffffu, rmax1, 2));

        const float mn0 = fmaxf(m2[0], rmax0);
        const float mn1 = fmaxf(m2[1], rmax1);
        const float al0 = __expf(m2[0] - mn0);
        const float al1 = __expf(m2[1] - mn1);
        m2[0] = mn0; m2[1] = mn1;

        // P = exp(S - m) with predicate zeroing (safe for fully-masked tiles)
        float rs0 = 0.f, rs1 = 0.f;
#pragma unroll
        for (int nt = 0; nt < 8; nt++) {
            const float p0 = (sacc[nt][0] > -1e29f) ? __expf(sacc[nt][0] - mn0) : 0.f;
            const float p1 = (sacc[nt][1] > -1e29f) ? __expf(sacc[nt][1] - mn0) : 0.f;
            const float p2 = (sacc[nt][2] > -1e29f) ? __expf(sacc[nt][2] - mn1) : 0.f;
            const float p3 = (sacc[nt][3] > -1e29f) ? __expf(sacc[nt][3] - mn1) : 0.f;
            rs0 += p0 + p1; rs1 += p2 + p3;
            uint2 u01 = make_uint2(f2tf32(p0), f2tf32(p1));
            uint2 u23 = make_uint2(f2tf32(p2), f2tf32(p3));
            *(uint2*)(&Ps[mb + r4    ][nt * 8 + 2 * c4]) = u01;
            *(uint2*)(&Ps[mb + r4 + 8][nt * 8 + 2 * c4]) = u23;
        }
        rs0 += __shfl_xor_sync(0xffffffffu, rs0, 1);
        rs0 += __shfl_xor_sync(0xffffffffu, rs0, 2);
        rs1 += __shfl_xor_sync(0xffffffffu, rs1, 1);
        rs1 += __shfl_xor_sync(0xffffffffu, rs1, 2);
        l2[0] = l2[0] * al0 + rs0;
        l2[1] = l2[1] * al1 + rs1;

#pragma unroll
        for (int dt = 0; dt < 8; dt++) {
            oacc[dt][0] *= al0; oacc[dt][1] *= al0;
            oacc[dt][2] *= al1; oacc[dt][3] *= al1;
        }
        __syncwarp();   // P stores visible to this warp's fragment loads

#pragma unroll
        for (int ks = 0; ks < 8; ks++) {
            uint32_t ap[4];
            ap[0] = Ps[mb + r4    ][ks * 8 + c4    ];
            ap[1] = Ps[mb + r4 + 8][ks * 8 + c4    ];
            ap[2] = Ps[mb + r4    ][ks * 8 + c4 + 4];
            ap[3] = Ps[mb + r4 + 8][ks * 8 + c4 + 4];
#pragma unroll
            for (int dt = 0; dt < 8; dt++) {
                uint32_t bv[2];
                bv[0] = Vs[ks * 8 + c4    ][dt * 8 + r4];
                bv[1] = Vs[ks * 8 + c4 + 4][dt * 8 + r4];
                mma16n8k8(oacc[dt], ap, bv);
            }
        }
    }

    const float inv0 = 1.0f / l2[0];
    const float inv1 = 1.0f / l2[1];
#pragma unroll
    for (int dt = 0; dt < 8; dt++) {
        const int d = dt * 8 + 2 * c4;
        float* o0 = g_attn + ((size_t)(b * SEQ + qi0) * HN + h) * HDIM + d;
        float* o1 = g_attn + ((size_t)(b * SEQ + qi1) * HN + h) * HDIM + d;
        *(float2*)o0 = make_float2(oacc[dt][0] * inv0, oacc[dt][1] * inv0);
        *(float2*)o1 = make_float2(oacc[dt][2] * inv1, oacc[dt][3] * inv1);
    }
}

// ---------------------------------------------------------------------------
extern "C" void kernel_launch(void* const* d_in, const int* in_sizes, int n_in,
                              void* d_out, int out_size)
{
    const float* hs = (const float*)d_in[0];
    const float* Wq = (const float*)d_in[1];
    const float* Wk = (const float*)d_in[2];
    const float* Wv = (const float*)d_in[3];
    const float* Wo = (const float*)d_in[4];
    float* out = (float*)d_out;

    float *qp, *kp, *vp, *ap;
    cudaGetSymbolAddress((void**)&qp, g_q);
    cudaGetSymbolAddress((void**)&kp, g_k);
    cudaGetSymbolAddress((void**)&vp, g_v);
    cudaGetSymbolAddress((void**)&ap, g_attn);

    const int M = BATCH * SEQ;   // 4096
    dim3 blk(256);

    build_rope_table<<<(SEQ * 32) / 256, 256>>>();

    // Fused QKV projections (cp.async double-buffered tf32 MMA)
    gemm_qkv<<<dim3((HN * HDIM) / 128, M / 128, 3), blk>>>(hs, Wq, Wk, Wv,
                                                           qp, kp, vp);

    // Attention (tf32 MMA flash, RoPE fused into staging)
    cudaFuncSetAttribute(attn_mma,
                         cudaFuncAttributeMaxDynamicSharedMemorySize,
                         ATTN_SMEM_BYTES);
    attn_mma<<<dim3(SEQ / 128, HN, BATCH), 256, ATTN_SMEM_BYTES>>>();

    // Output projection
    gemm_out<<<dim3(DM / 128, M / 128), blk>>>(ap, Wo, out);
}

// round 12
// speedup vs baseline: 1.1417x; 1.1417x over previous
#include <cuda_runtime.h>
#include <math.h>
#include <stdint.h>

#define HN   16
#define KVN  8
#define HDIM 64
#define WIN  512
#define BATCH 2
#define SEQ  2048
#define DM   1024

// Scratch — layouts:
// g_q: [B, HN, S, 64] (pre-RoPE), g_k/g_v: [B, KVN, S, 64] (pre-RoPE),
// g_attn: [B*S, HN*64]
__device__ float g_q[(size_t)BATCH * HN * SEQ * HDIM];
__device__ float g_k[(size_t)BATCH * KVN * SEQ * HDIM];
__device__ float g_v[(size_t)BATCH * KVN * SEQ * HDIM];
__device__ float g_attn[(size_t)BATCH * SEQ * HN * HDIM];
// RoPE tables: [SEQ][32]
__device__ float g_cos[SEQ * 32];
__device__ float g_sin[SEQ * 32];

// ---------------------------------------------------------------------------
__global__ void build_rope_table()
{
    const int idx = blockIdx.x * blockDim.x + threadIdx.x;
    if (idx >= SEQ * 32) return;
    const int p = idx & 31;
    const int s = idx >> 5;
    const double invf = pow(10000.0, -((double)(2 * p)) / 64.0);
    const double ang = (double)s * invf;
    g_cos[idx] = (float)cos(ang);
    g_sin[idx] = (float)sin(ang);
}

// ---------------------------------------------------------------------------
__device__ __forceinline__ uint32_t f2tf32(float f) {
    uint32_t u;
    asm("cvt.rna.tf32.f32 %0, %1;" : "=r"(u) : "f"(f));
    return u;
}

__device__ __forceinline__ void mma16n8k8(float* d, const uint32_t* a,
                                          const uint32_t* b) {
    asm("mma.sync.aligned.m16n8k8.row.col.f32.tf32.tf32.f32 "
        "{%0,%1,%2,%3}, {%4,%5,%6,%7}, {%8,%9}, {%0,%1,%2,%3};"
        : "+f"(d[0]), "+f"(d[1]), "+f"(d[2]), "+f"(d[3])
        : "r"(a[0]), "r"(a[1]), "r"(a[2]), "r"(a[3]),
          "r"(b[0]), "r"(b[1]));
}

#define CP_ASYNC16(dst_u32, src_ptr) \
    asm volatile("cp.async.ca.shared.global [%0], [%1], 16;" \
                 :: "r"(dst_u32), "l"(src_ptr))
#define CP_COMMIT() asm volatile("cp.async.commit_group;")
#define CP_WAIT(n)  asm volatile("cp.async.wait_group %0;" :: "n"(n))

// ---------------------------------------------------------------------------
// tf32 GEMM: C = A[M,K] @ B[K,N]. BM=128, BN=256, BK=16, 256 thr = 8 warps
// as 2(wy) x 4(wx); warp tile 64x64 (4 mt x 8 nt of m16n8k8).
// Double-buffered cp.async (validated R10). fp32 smem, cvt at fragment load.
// As[2][128][20]: banks 20*r4+c4 all-distinct. Bs[2][16][264]: banks 8*c4+r4.
// MODE 0: linear C. MODE 1: scatter to [B, NH, S, 64] head layout.
// Dynamic smem: 2*128*20*4 + 2*16*264*4 = 54272 B.
// ---------------------------------------------------------------------------
#define GEMM_SMEM_BYTES (2 * 128 * 20 * 4 + 2 * 16 * 264 * 4)

template <int MODE>
__device__ __forceinline__ void gemm_body(
    const float* __restrict__ A, const float* __restrict__ Bm,
    float* __restrict__ C, int M, int N, int K, int NH)
{
    extern __shared__ float gsm[];
    float (*As)[128][20] = (float(*)[128][20])(gsm);
    float (*Bs)[16][264] = (float(*)[16][264])(gsm + 2 * 128 * 20);

    const int tid  = threadIdx.x;
    const int lane = tid & 31;
    const int wid  = tid >> 5;
    const int wy   = wid >> 2;          // 0..1 -> m offset wy*64
    const int wx   = wid & 3;           // 0..3 -> n offset wx*64
    const int r4   = lane >> 2;
    const int c4   = lane & 3;
    const int m0   = blockIdx.y * 128, n0 = blockIdx.x * 256;

    const int NT = K / 16;

    // prologue: tile 0 -> buffer 0
    {
#pragma unroll
        for (int i0 = 0; i0 < 4; i0++) {
            const int i = tid + i0 * 256;          // 0..1023
            if (i < 512) {                          // A: 128x16 = 512 f4
                const int r = i >> 2, c = (i & 3) * 4;
                CP_ASYNC16((uint32_t)__cvta_generic_to_shared(&As[0][r][c]),
                           A + (size_t)(m0 + r) * K + c);
            }
            const int br = i >> 6, bc = (i & 63) * 4;  // B: 16x256 = 1024 f4
            CP_ASYNC16((uint32_t)__cvta_generic_to_shared(&Bs[0][br][bc]),
                       Bm + (size_t)br * N + n0 + bc);
        }
        CP_COMMIT();
    }

    float acc[4][8][4] = {};
    int buf = 0;

    for (int kt = 0; kt < NT; kt++) {
        if (kt + 1 < NT) {
            const int k0 = (kt + 1) * 16;
            const int nb = buf ^ 1;
#pragma unroll
            for (int i0 = 0; i0 < 4; i0++) {
                const int i = tid + i0 * 256;
                if (i < 512) {
                    const int r = i >> 2, c = (i & 3) * 4;
                    CP_ASYNC16((uint32_t)__cvta_generic_to_shared(&As[nb][r][c]),
                               A + (size_t)(m0 + r) * K + k0 + c);
                }
                const int br = i >> 6, bc = (i & 63) * 4;
                CP_ASYNC16((uint32_t)__cvta_generic_to_shared(&Bs[nb][br][bc]),
                           Bm + (size_t)(k0 + br) * N + n0 + bc);
            }
            CP_COMMIT();
            CP_WAIT(1);
        } else {
            CP_WAIT(0);
        }
        __syncthreads();

#pragma unroll
        for (int kk = 0; kk < 16; kk += 8) {
            uint32_t af[4][4], bf[8][2];
#pragma unroll
            for (int mt = 0; mt < 4; mt++) {
                const int mb = wy * 64 + mt * 16;
                af[mt][0] = f2tf32(As[buf][mb + r4    ][kk + c4    ]);
                af[mt][1] = f2tf32(As[buf][mb + r4 + 8][kk + c4    ]);
                af[mt][2] = f2tf32(As[buf][mb + r4    ][kk + c4 + 4]);
                af[mt][3] = f2tf32(As[buf][mb + r4 + 8][kk + c4 + 4]);
            }
#pragma unroll
            for (int nt = 0; nt < 8; nt++) {
                const int nb2 = wx * 64 + nt * 8;
                bf[nt][0] = f2tf32(Bs[buf][kk + c4    ][nb2 + r4]);
                bf[nt][1] = f2tf32(Bs[buf][kk + c4 + 4][nb2 + r4]);
            }
#pragma unroll
            for (int mt = 0; mt < 4; mt++)
#pragma unroll
                for (int nt = 0; nt < 8; nt++)
                    mma16n8k8(acc[mt][nt], af[mt], bf[nt]);
        }
        __syncthreads();
        buf ^= 1;
    }

#pragma unroll
    for (int mt = 0; mt < 4; mt++) {
#pragma unroll
        for (int nt = 0; nt < 8; nt++) {
            const int m = m0 + wy * 64 + mt * 16 + r4;
            const int n = n0 + wx * 64 + nt * 8 + 2 * c4;
#pragma unroll
            for (int half = 0; half < 2; half++) {
                const int mr = m + half * 8;
                float2 o = make_float2(acc[mt][nt][half * 2],
                                       acc[mt][nt][half * 2 + 1]);
                if (MODE == 0) {
                    *(float2*)(C + (size_t)mr * N + n) = o;
                } else {
                    const int b = mr / SEQ, s = mr % SEQ;
                    const int h = n >> 6, d = n & 63;
                    *(float2*)(C + (((size_t)(b * NH + h)) * SEQ + s) * HDIM + d) = o;
                }
            }
        }
    }
}

__global__ void __launch_bounds__(256, 1)
gemm_qkv(const float* __restrict__ hs,
         const float* __restrict__ Wq, const float* __restrict__ Wk,
         const float* __restrict__ Wv,
         float* __restrict__ qp, float* __restrict__ kp, float* __restrict__ vp)
{
    const int z = blockIdx.z;
    const float* Bm; float* C; int N, NH;
    if (z == 0)      { Bm = Wq; C = qp; N = HN  * HDIM; NH = HN;  }
    else if (z == 1) { Bm = Wk; C = kp; N = KVN * HDIM; NH = KVN; }
    else             { Bm = Wv; C = vp; N = KVN * HDIM; NH = KVN; }
    if (blockIdx.x * 256 >= N) return;
    gemm_body<1>(hs, Bm, C, BATCH * SEQ, N, DM, NH);
}

__global__ void __launch_bounds__(256, 1)
gemm_out(const float* __restrict__ A, const float* __restrict__ Bm,
         float* __restrict__ C)
{
    gemm_body<0>(A, Bm, C, BATCH * SEQ, DM, DM, 0);
}

// ---------------------------------------------------------------------------
// MMA flash attention (R10 structure — validated at 338.7us) with fused RoPE
// staging from the table. 128 threads = 4 warps, one 64-query tile.
// Smem: Ps[64][72], Ks[64][72], Vs[64][72] = 54 KB dynamic.
// ---------------------------------------------------------------------------
#define ATS 72
#define ATTN_SMEM_BYTES (3 * 64 * ATS * 4)

__global__ void __launch_bounds__(128) attn_mma()
{
    extern __shared__ uint32_t smu[];
    uint32_t (*Ps)[ATS] = (uint32_t(*)[ATS])(smu);
    uint32_t (*Ks)[ATS] = (uint32_t(*)[ATS])(smu + 64 * ATS);
    uint32_t (*Vs)[ATS] = (uint32_t(*)[ATS])(smu + 2 * 64 * ATS);

    const int b = blockIdx.z, h = blockIdx.y;
    const int qb = blockIdx.x * 64;
    const int kvh = h >> 1;            // n_rep = 2
    const int tid  = threadIdx.x;
    const int lane = tid & 31;
    const int wid  = tid >> 5;
    const int mb   = wid * 16;
    const int r4   = lane >> 2;
    const int c4   = lane & 3;

    const float* qg = g_q + ((size_t)(b * HN + h) * SEQ + qb) * HDIM;
    const float* kg = g_k + (size_t)(b * KVN + kvh) * SEQ * HDIM;
    const float* vg = g_v + (size_t)(b * KVN + kvh) * SEQ * HDIM;

    // Stage Q with fused RoPE + 0.125 scale (64 rows x 8 f4 of cols<32).
    for (int i = tid; i < 64 * 8; i += 128) {
        const int row = i >> 3;
        const int col = (i & 7) * 4;
        const float4 x1 = *(const float4*)(qg + row * HDIM + col);
        const float4 x2 = *(const float4*)(qg + row * HDIM + col + 32);
        const float4 cc = *(const float4*)(&g_cos[(qb + row) * 32 + col]);
        const float4 ss = *(const float4*)(&g_sin[(qb + row) * 32 + col]);
        Ps[row][col + 0]  = f2tf32((x1.x * cc.x - x2.x * ss.x) * 0.125f);
        Ps[row][col + 1]  = f2tf32((x1.y * cc.y - x2.y * ss.y) * 0.125f);
        Ps[row][col + 2]  = f2tf32((x1.z * cc.z - x2.z * ss.z) * 0.125f);
        Ps[row][col + 3]  = f2tf32((x1.w * cc.w - x2.w * ss.w) * 0.125f);
        Ps[row][col + 32] = f2tf32((x2.x * cc.x + x1.x * ss.x) * 0.125f);
        Ps[row][col + 33] = f2tf32((x2.y * cc.y + x1.y * ss.y) * 0.125f);
        Ps[row][col + 34] = f2tf32((x2.z * cc.z + x1.z * ss.z) * 0.125f);
        Ps[row][col + 35] = f2tf32((x2.w * cc.w + x1.w * ss.w) * 0.125f);
    }
    __syncthreads();

    uint32_t aq[8][4];
#pragma unroll
    for (int ks = 0; ks < 8; ks++) {
        aq[ks][0] = Ps[mb + r4    ][ks * 8 + c4    ];
        aq[ks][1] = Ps[mb + r4 + 8][ks * 8 + c4    ];
        aq[ks][2] = Ps[mb + r4    ][ks * 8 + c4 + 4];
        aq[ks][3] = Ps[mb + r4 + 8][ks * 8 + c4 + 4];
    }

    float oacc[8][4] = {};
    float m2[2] = {-1e30f, -1e30f};
    float l2[2] = {0.0f, 0.0f};
    const int qi0 = qb + mb + r4;
    const int qi1 = qi0 + 8;

    const int kstart = (qb >= WIN) ? (qb - WIN) : 0;

    for (int kb = kstart; kb <= qb; kb += 64) {
        __syncthreads();
        // K staging with fused RoPE; V staging plain.
        for (int i = tid; i < 64 * 8; i += 128) {
            const int row = i >> 3;
            const int col = (i & 7) * 4;
            const float4 x1 = *(const float4*)(kg + (size_t)(kb + row) * HDIM + col);
            const float4 x2 = *(const float4*)(kg + (size_t)(kb + row) * HDIM + col + 32);
            const float4 cc = *(const float4*)(&g_cos[(kb + row) * 32 + col]);
            const float4 ss = *(const float4*)(&g_sin[(kb + row) * 32 + col]);
            Ks[row][col + 0]  = f2tf32(x1.x * cc.x - x2.x * ss.x);
            Ks[row][col + 1]  = f2tf32(x1.y * cc.y - x2.y * ss.y);
            Ks[row][col + 2]  = f2tf32(x1.z * cc.z - x2.z * ss.z);
            Ks[row][col + 3]  = f2tf32(x1.w * cc.w - x2.w * ss.w);
            Ks[row][col + 32] = f2tf32(x2.x * cc.x + x1.x * ss.x);
            Ks[row][col + 33] = f2tf32(x2.y * cc.y + x1.y * ss.y);
            Ks[row][col + 34] = f2tf32(x2.z * cc.z + x1.z * ss.z);
            Ks[row][col + 35] = f2tf32(x2.w * cc.w + x1.w * ss.w);
        }
        for (int i = tid; i < 64 * 16; i += 128) {
            const int f = i * 4;
            const int row = f >> 6, col = f & 63;
            float4 vv = *(const float4*)(vg + (size_t)kb * HDIM + f);
            Vs[row][col + 0] = f2tf32(vv.x); Vs[row][col + 1] = f2tf32(vv.y);
            Vs[row][col + 2] = f2tf32(vv.z); Vs[row][col + 3] = f2tf32(vv.w);
        }
        __syncthreads();

        float sacc[8][4] = {};
#pragma unroll
        for (int ks = 0; ks < 8; ks++) {
#pragma unroll
            for (int nt = 0; nt < 8; nt++) {
                uint32_t bk[2];
                bk[0] = Ks[nt * 8 + r4][ks * 8 + c4    ];
                bk[1] = Ks[nt * 8 + r4][ks * 8 + c4 + 4];
                mma16n8k8(sacc[nt], aq[ks], bk);
            }
        }

        float rmax0 = -1e30f, rmax1 = -1e30f;
#pragma unroll
        for (int nt = 0; nt < 8; nt++) {
            const int kj = kb + nt * 8 + 2 * c4;
            if (!((kj     <= qi0) && (kj     + WIN >= qi0))) sacc[nt][0] = -1e30f;
            if (!((kj + 1 <= qi0) && (kj + 1 + WIN >= qi0))) sacc[nt][1] = -1e30f;
            if (!((kj     <= qi1) && (kj     + WIN >= qi1))) sacc[nt][2] = -1e30f;
            if (!((kj + 1 <= qi1) && (kj + 1 + WIN >= qi1))) sacc[nt][3] = -1e30f;
            rmax0 = fmaxf(rmax0, fmaxf(sacc[nt][0], sacc[nt][1]));
            rmax1 = fmaxf(rmax1, fmaxf(sacc[nt][2], sacc[nt][3]));
        }
        rmax0 = fmaxf(rmax0, __shfl_xor_sync(0xffffffffu, rmax0, 1));
        rmax0 = fmaxf(rmax0, __shfl_xor_sync(0xffffffffu, rmax0, 2));
        rmax1 = fmaxf(rmax1, __shfl_xor_sync(0xffffffffu, rmax1, 1));
        rmax1 = fmaxf(rmax1, __shfl_xor_sync(0xffffffffu, rmax1, 2));

        const float mn0 = fmaxf(m2[0], rmax0);
        const float mn1 = fmaxf(m2[1], rmax1);
        const float al0 = __expf(m2[0] - mn0);
        const float al1 = __expf(m2[1] - mn1);
        m2[0] = mn0; m2[1] = mn1;

        float rs0 = 0.f, rs1 = 0.f;
#pragma unroll
        for (int nt = 0; nt < 8; nt++) {
            const float p0 = (sacc[nt][0] > -1e29f) ? __expf(sacc[nt][0] - mn0) : 0.f;
            const float p1 = (sacc[nt][1] > -1e29f) ? __expf(sacc[nt][1] - mn0) : 0.f;
            const float p2 = (sacc[nt][2] > -1e29f) ? __expf(sacc[nt][2] - mn1) : 0.f;
            const float p3 = (sacc[nt][3] > -1e29f) ? __expf(sacc[nt][3] - mn1) : 0.f;
            rs0 += p0 + p1; rs1 += p2 + p3;
            uint2 u01 = make_uint2(f2tf32(p0), f2tf32(p1));
            uint2 u23 = make_uint2(f2tf32(p2), f2tf32(p3));
            *(uint2*)(&Ps[mb + r4    ][nt * 8 + 2 * c4]) = u01;
            *(uint2*)(&Ps[mb + r4 + 8][nt * 8 + 2 * c4]) = u23;
        }
        rs0 += __shfl_xor_sync(0xffffffffu, rs0, 1);
        rs0 += __shfl_xor_sync(0xffffffffu, rs0, 2);
        rs1 += __shfl_xor_sync(0xffffffffu, rs1, 1);
        rs1 += __shfl_xor_sync(0xffffffffu, rs1, 2);
        l2[0] = l2[0] * al0 + rs0;
        l2[1] = l2[1] * al1 + rs1;

#pragma unroll
        for (int dt = 0; dt < 8; dt++) {
            oacc[dt][0] *= al0; oacc[dt][1] *= al0;
            oacc[dt][2] *= al1; oacc[dt][3] *= al1;
        }
        __syncwarp();

#pragma unroll
        for (int ks = 0; ks < 8; ks++) {
            uint32_t ap[4];
            ap[0] = Ps[mb + r4    ][ks * 8 + c4    ];
            ap[1] = Ps[mb + r4 + 8][ks * 8 + c4    ];
            ap[2] = Ps[mb + r4    ][ks * 8 + c4 + 4];
            ap[3] = Ps[mb + r4 + 8][ks * 8 + c4 + 4];
#pragma unroll
            for (int dt = 0; dt < 8; dt++) {
                uint32_t bv[2];
                bv[0] = Vs[ks * 8 + c4    ][dt * 8 + r4];
                bv[1] = Vs[ks * 8 + c4 + 4][dt * 8 + r4];
                mma16n8k8(oacc[dt], ap, bv);
            }
        }
    }

    const float inv0 = 1.0f / l2[0];
    const float inv1 = 1.0f / l2[1];
#pragma unroll
    for (int dt = 0; dt < 8; dt++) {
        const int d = dt * 8 + 2 * c4;
        float* o0 = g_attn + ((size_t)(b * SEQ + qi0) * HN + h) * HDIM + d;
        float* o1 = g_attn + ((size_t)(b * SEQ + qi1) * HN + h) * HDIM + d;
        *(float2*)o0 = make_float2(oacc[dt][0] * inv0, oacc[dt][1] * inv0);
        *(float2*)o1 = make_float2(oacc[dt][2] * inv1, oacc[dt][3] * inv1);
    }
}

// ---------------------------------------------------------------------------
extern "C" void kernel_launch(void* const* d_in, const int* in_sizes, int n_in,
                              void* d_out, int out_size)
{
    const float* hs = (const float*)d_in[0];
    const float* Wq = (const float*)d_in[1];
    const float* Wk = (const float*)d_in[2];
    const float* Wv = (const float*)d_in[3];
    const float* Wo = (const float*)d_in[4];
    float* out = (float*)d_out;

    float *qp, *kp, *vp, *ap;
    cudaGetSymbolAddress((void**)&qp, g_q);
    cudaGetSymbolAddress((void**)&kp, g_k);
    cudaGetSymbolAddress((void**)&vp, g_v);
    cudaGetSymbolAddress((void**)&ap, g_attn);

    const int M = BATCH * SEQ;   // 4096
    dim3 blk(256);

    build_rope_table<<<(SEQ * 32) / 256, 256>>>();

    cudaFuncSetAttribute(gemm_qkv,
                         cudaFuncAttributeMaxDynamicSharedMemorySize,
                         GEMM_SMEM_BYTES);
    cudaFuncSetAttribute(gemm_out,
                         cudaFuncAttributeMaxDynamicSharedMemorySize,
                         GEMM_SMEM_BYTES);

    // Fused QKV projections (BN=256, warp tile 64x64)
    gemm_qkv<<<dim3((HN * HDIM) / 256, M / 128, 3), blk, GEMM_SMEM_BYTES>>>(
        hs, Wq, Wk, Wv, qp, kp, vp);

    // Attention (tf32 MMA flash, 64-q tiles, fused RoPE staging)
    cudaFuncSetAttribute(attn_mma,
                         cudaFuncAttributeMaxDynamicSharedMemorySize,
                         ATTN_SMEM_BYTES);
    attn_mma<<<dim3(SEQ / 64, HN, BATCH), 128, ATTN_SMEM_BYTES>>>();

    // Output projection
    gemm_out<<<dim3(DM / 256, M / 128), blk, GEMM_SMEM_BYTES>>>(ap, Wo, out);
}

// round 14
// speedup vs baseline: 1.4841x; 1.2999x over previous
#include <cuda_runtime.h>
#include <cuda_fp16.h>
#include <math.h>
#include <stdint.h>

#define HN   16
#define KVN  8
#define HDIM 64
#define WIN  512
#define BATCH 2
#define SEQ  2048
#define DM   1024

// Scratch (half precision operands for fp16 MMA GEMMs):
// g_q: [B, HN, S, 64], g_k/g_v: [B, KVN, S, 64] (pre-RoPE, half)
// g_attn: [B*S, HN*64] half; g_hsh: hs in half; g_wth: W^T pack in half [n][k]
__device__ __half g_q[(size_t)BATCH * HN * SEQ * HDIM];
__device__ __half g_k[(size_t)BATCH * KVN * SEQ * HDIM];
__device__ __half g_v[(size_t)BATCH * KVN * SEQ * HDIM];
__device__ __half g_attn[(size_t)BATCH * SEQ * HN * HDIM];
__device__ __half g_hsh[(size_t)BATCH * SEQ * DM];
#define WT_Q 0
#define WT_K (1024 * 1024)
#define WT_V (1024 * 1024 + 512 * 1024)
#define WT_O (1024 * 1024 + 2 * 512 * 1024)
__device__ __half g_wth[1024 * 1024 + 2 * 512 * 1024 + 1024 * 1024];
__device__ float g_cos[SEQ * 32];
__device__ float g_sin[SEQ * 32];

// ---------------------------------------------------------------------------
__global__ void build_rope_table()
{
    const int idx = blockIdx.x * blockDim.x + threadIdx.x;
    if (idx >= SEQ * 32) return;
    const int p = idx & 31;
    const int s = idx >> 5;
    const double invf = pow(10000.0, -((double)(2 * p)) / 64.0);
    const double ang = (double)s * invf;
    g_cos[idx] = (float)cos(ang);
    g_sin[idx] = (float)sin(ang);
}

// ---------------------------------------------------------------------------
__device__ __forceinline__ uint32_t f2tf32(float f) {
    uint32_t u;
    asm("cvt.rna.tf32.f32 %0, %1;" : "=r"(u) : "f"(f));
    return u;
}

// tf32 m16n8k8 (attention — validated R9-R12)
__device__ __forceinline__ void mma16n8k8(float* d, const uint32_t* a,
                                          const uint32_t* b) {
    asm("mma.sync.aligned.m16n8k8.row.col.f32.tf32.tf32.f32 "
        "{%0,%1,%2,%3}, {%4,%5,%6,%7}, {%8,%9}, {%0,%1,%2,%3};"
        : "+f"(d[0]), "+f"(d[1]), "+f"(d[2]), "+f"(d[3])
        : "r"(a[0]), "r"(a[1]), "r"(a[2]), "r"(a[3]),
          "r"(b[0]), "r"(b[1]));
}

// fp16 m16n8k16, f32 accumulate (GEMMs)
__device__ __forceinline__ void mma16n8k16h(float* d, const uint32_t* a,
                                            const uint32_t* b) {
    asm("mma.sync.aligned.m16n8k16.row.col.f32.f16.f16.f32 "
        "{%0,%1,%2,%3}, {%4,%5,%6,%7}, {%8,%9}, {%0,%1,%2,%3};"
        : "+f"(d[0]), "+f"(d[1]), "+f"(d[2]), "+f"(d[3])
        : "r"(a[0]), "r"(a[1]), "r"(a[2]), "r"(a[3]),
          "r"(b[0]), "r"(b[1]));
}

#define CP_ASYNC16(dst_u32, src_ptr) \
    asm volatile("cp.async.ca.shared.global [%0], [%1], 16;" \
                 :: "r"(dst_u32), "l"(src_ptr))
#define CP_COMMIT() asm volatile("cp.async.commit_group;")
#define CP_WAIT(n)  asm volatile("cp.async.wait_group %0;" :: "n"(n))

// load 4 halves -> float4
__device__ __forceinline__ float4 ld4h(const __half* p) {
    uint2 u = *(const uint2*)p;
    __half2 h0 = *(__half2*)&u.x, h1 = *(__half2*)&u.y;
    float2 f0 = __half22float2(h0), f1 = __half22float2(h1);
    return make_float4(f0.x, f0.y, f1.x, f1.y);
}

// ---------------------------------------------------------------------------
// Prep: hs -> half; W -> W^T half ([n][k], k contiguous).
// ---------------------------------------------------------------------------
__global__ void conv_hs(const float* __restrict__ in, __half* __restrict__ outp)
{
    const int i = blockIdx.x * 256 + threadIdx.x;   // float4 index
    float4 v = ((const float4*)in)[i];
    __half2 h0 = __floats2half2_rn(v.x, v.y);
    __half2 h1 = __floats2half2_rn(v.z, v.w);
    uint2 u;
    u.x = *(uint32_t*)&h0; u.y = *(uint32_t*)&h1;
    *(uint2*)(outp + (size_t)i * 4) = u;
}

__global__ void transpose_w_h(const float* __restrict__ Wq,
                              const float* __restrict__ Wk,
                              const float* __restrict__ Wv,
                              const float* __restrict__ Wo)
{
    const int z = blockIdx.z;
    const float* W; __half* T; int N;
    if (z == 0)      { W = Wq; T = g_wth + WT_Q; N = 1024; }
    else if (z == 1) { W = Wk; T = g_wth + WT_K; N = 512; }
    else if (z == 2) { W = Wv; T = g_wth + WT_V; N = 512; }
    else             { W = Wo; T = g_wth + WT_O; N = 1024; }
    if (blockIdx.x * 32 >= N) return;

    __shared__ float t[32][33];
    const int n0 = blockIdx.x * 32, k0 = blockIdx.y * 32;
    const int tx = threadIdx.x & 31, ty = threadIdx.x >> 5;   // 32x8
#pragma unroll
    for (int r = 0; r < 4; r++)
        t[ty + r * 8][tx] = W[(size_t)(k0 + ty + r * 8) * N + n0 + tx];
    __syncthreads();
#pragma unroll
    for (int r = 0; r < 4; r++)
        T[(size_t)(n0 + ty + r * 8) * 1024 + k0 + tx] = __float2half(t[tx][ty + r * 8]);
}

// ---------------------------------------------------------------------------
// fp16 tensor-core GEMM: C = A[M,K]h @ W, B given as W^T [N,K]h (k contig).
// BM=BN=128, BK=32, 256 thr = 8 warps (2 wy x 4 wx), warp tile 64x32 via
// m16n8k16. Double-buffered cp.async. Smem rows stride 40 halves (20 words):
// fragment banks 20*r4+c4 (+4/+8) all-distinct -> conflict-free.
// MODE 0: float C, linear (N=1024). MODE 1: half C, scatter [B,NH,S,64].
// ---------------------------------------------------------------------------
template <int MODE>
__device__ __forceinline__ void gemm_body(
    const __half* __restrict__ A, const __half* __restrict__ BT,
    void* __restrict__ C, int N, int NH)
{
    __shared__ __half Ah[2][128][40];
    __shared__ __half Bh[2][128][40];

    const int K = DM;
    const int tid  = threadIdx.x;
    const int lane = tid & 31;
    const int wid  = tid >> 5;
    const int wy   = wid >> 2;          // 0..1
    const int wx   = wid & 3;           // 0..3
    const int r4   = lane >> 2;
    const int c4   = lane & 3;
    const int m0   = blockIdx.y * 128, n0 = blockIdx.x * 128;

    const __half* Ab = A + (size_t)m0 * K;
    const __half* Bb = BT + (size_t)n0 * K;

#define GF_FILL(buf, kt) do {                                                 \
    _Pragma("unroll")                                                         \
    for (int i0 = 0; i0 < 2; i0++) {                                          \
        const int i = tid + i0 * 256;                                         \
        const int r = i >> 2, c = (i & 3) * 8;                                \
        CP_ASYNC16((uint32_t)__cvta_generic_to_shared(&Ah[buf][r][c]),        \
                   Ab + (size_t)r * K + (kt) * 32 + c);                       \
        CP_ASYNC16((uint32_t)__cvta_generic_to_shared(&Bh[buf][r][c]),        \
                   Bb + (size_t)r * K + (kt) * 32 + c);                       \
    }                                                                         \
    CP_COMMIT();                                                              \
} while (0)

    GF_FILL(0, 0);

    float acc[4][4][4] = {};
    int buf = 0;
    const int NT = K / 32;

    for (int kt = 0; kt < NT; kt++) {
        if (kt + 1 < NT) {
            GF_FILL(buf ^ 1, kt + 1);
            CP_WAIT(1);
        } else {
            CP_WAIT(0);
        }
        __syncthreads();

#pragma unroll
        for (int ks2 = 0; ks2 < 2; ks2++) {
            const int bw = ks2 * 8;     // word base within row
            uint32_t af[4][4], bf[4][2];
#pragma unroll
            for (int mt = 0; mt < 4; mt++) {
                const int mb = wy * 64 + mt * 16;
                const uint32_t* r0 = (const uint32_t*)&Ah[buf][mb + r4][0];
                const uint32_t* r1 = (const uint32_t*)&Ah[buf][mb + r4 + 8][0];
                af[mt][0] = r0[bw + c4];
                af[mt][1] = r1[bw + c4];
                af[mt][2] = r0[bw + c4 + 4];
                af[mt][3] = r1[bw + c4 + 4];
            }
#pragma unroll
            for (int nt = 0; nt < 4; nt++) {
                const int nb = wx * 32 + nt * 8;
                const uint32_t* rn = (const uint32_t*)&Bh[buf][nb + r4][0];
                bf[nt][0] = rn[bw + c4];
                bf[nt][1] = rn[bw + c4 + 4];
            }
#pragma unroll
            for (int mt = 0; mt < 4; mt++)
#pragma unroll
                for (int nt = 0; nt < 4; nt++)
                    mma16n8k16h(acc[mt][nt], af[mt], bf[nt]);
        }
        __syncthreads();
        buf ^= 1;
    }
#undef GF_FILL

#pragma unroll
    for (int mt = 0; mt < 4; mt++) {
#pragma unroll
        for (int nt = 0; nt < 4; nt++) {
            const int m = m0 + wy * 64 + mt * 16 + r4;
            const int n = n0 + wx * 32 + nt * 8 + 2 * c4;
#pragma unroll
            for (int half_ = 0; half_ < 2; half_++) {
                const int mr = m + half_ * 8;
                const float v0 = acc[mt][nt][half_ * 2];
                const float v1 = acc[mt][nt][half_ * 2 + 1];
                if (MODE == 0) {
                    *(float2*)((float*)C + (size_t)mr * DM + n) =
                        make_float2(v0, v1);
                } else {
                    const int b = mr / SEQ, s = mr % SEQ;
                    const int h = n >> 6, d = n & 63;
                    *(__half2*)((__half*)C +
                        (((size_t)(b * NH + h)) * SEQ + s) * HDIM + d) =
                        __floats2half2_rn(v0, v1);
                }
            }
        }
    }
}

__global__ void __launch_bounds__(256, 2)
gemm_qkv(const __half* __restrict__ hsh)
{
    const int z = blockIdx.z;
    const __half* BT; __half* C; int N, NH;
    if (z == 0)      { BT = g_wth + WT_Q; C = g_q; N = 1024; NH = HN;  }
    else if (z == 1) { BT = g_wth + WT_K; C = g_k; N = 512;  NH = KVN; }
    else             { BT = g_wth + WT_V; C = g_v; N = 512;  NH = KVN; }
    if (blockIdx.x * 128 >= N) return;
    gemm_body<1>(hsh, BT, C, N, NH);
}

__global__ void __launch_bounds__(256, 2)
gemm_out(float* __restrict__ out)
{
    gemm_body<0>(g_attn, g_wth + WT_O, out, 1024, 0);
}

// ---------------------------------------------------------------------------
// MMA flash attention (validated R10/R12): 128 threads = 4 warps, 64-q tile,
// fused RoPE staging; q/k/v read as half, staged tf32; output half -> g_attn.
// ---------------------------------------------------------------------------
#define ATS 72
#define ATTN_SMEM_BYTES (3 * 64 * ATS * 4)

__global__ void __launch_bounds__(128) attn_mma()
{
    extern __shared__ uint32_t smu[];
    uint32_t (*Ps)[ATS] = (uint32_t(*)[ATS])(smu);
    uint32_t (*Ks)[ATS] = (uint32_t(*)[ATS])(smu + 64 * ATS);
    uint32_t (*Vs)[ATS] = (uint32_t(*)[ATS])(smu + 2 * 64 * ATS);

    const int b = blockIdx.z, h = blockIdx.y;
    const int qb = blockIdx.x * 64;
    const int kvh = h >> 1;
    const int tid  = threadIdx.x;
    const int lane = tid & 31;
    const int wid  = tid >> 5;
    const int mb   = wid * 16;
    const int r4   = lane >> 2;
    const int c4   = lane & 3;

    const __half* qg = g_q + ((size_t)(b * HN + h) * SEQ + qb) * HDIM;
    const __half* kg = g_k + (size_t)(b * KVN + kvh) * SEQ * HDIM;
    const __half* vg = g_v + (size_t)(b * KVN + kvh) * SEQ * HDIM;

    for (int i = tid; i < 64 * 8; i += 128) {
        const int row = i >> 3;
        const int col = (i & 7) * 4;
        const float4 x1 = ld4h(qg + row * HDIM + col);
        const float4 x2 = ld4h(qg + row * HDIM + col + 32);
        const float4 cc = *(const float4*)(&g_cos[(qb + row) * 32 + col]);
        const float4 ss = *(const float4*)(&g_sin[(qb + row) * 32 + col]);
        Ps[row][col + 0]  = f2tf32((x1.x * cc.x - x2.x * ss.x) * 0.125f);
        Ps[row][col + 1]  = f2tf32((x1.y * cc.y - x2.y * ss.y) * 0.125f);
        Ps[row][col + 2]  = f2tf32((x1.z * cc.z - x2.z * ss.z) * 0.125f);
        Ps[row][col + 3]  = f2tf32((x1.w * cc.w - x2.w * ss.w) * 0.125f);
        Ps[row][col + 32] = f2tf32((x2.x * cc.x + x1.x * ss.x) * 0.125f);
        Ps[row][col + 33] = f2tf32((x2.y * cc.y + x1.y * ss.y) * 0.125f);
        Ps[row][col + 34] = f2tf32((x2.z * cc.z + x1.z * ss.z) * 0.125f);
        Ps[row][col + 35] = f2tf32((x2.w * cc.w + x1.w * ss.w) * 0.125f);
    }
    __syncthreads();

    uint32_t aq[8][4];
#pragma unroll
    for (int ks = 0; ks < 8; ks++) {
        aq[ks][0] = Ps[mb + r4    ][ks * 8 + c4    ];
        aq[ks][1] = Ps[mb + r4 + 8][ks * 8 + c4    ];
        aq[ks][2] = Ps[mb + r4    ][ks * 8 + c4 + 4];
        aq[ks][3] = Ps[mb + r4 + 8][ks * 8 + c4 + 4];
    }

    float oacc[8][4] = {};
    float m2[2] = {-1e30f, -1e30f};
    float l2[2] = {0.0f, 0.0f};
    const int qi0 = qb + mb + r4;
    const int qi1 = qi0 + 8;

    const int kstart = (qb >= WIN) ? (qb - WIN) : 0;

    for (int kb = kstart; kb <= qb; kb += 64) {
        __syncthreads();
        for (int i = tid; i < 64 * 8; i += 128) {
            const int row = i >> 3;
            const int col = (i & 7) * 4;
            const float4 x1 = ld4h(kg + (size_t)(kb + row) * HDIM + col);
            const float4 x2 = ld4h(kg + (size_t)(kb + row) * HDIM + col + 32);
            const float4 cc = *(const float4*)(&g_cos[(kb + row) * 32 + col]);
            const float4 ss = *(const float4*)(&g_sin[(kb + row) * 32 + col]);
            Ks[row][col + 0]  = f2tf32(x1.x * cc.x - x2.x * ss.x);
            Ks[row][col + 1]  = f2tf32(x1.y * cc.y - x2.y * ss.y);
            Ks[row][col + 2]  = f2tf32(x1.z * cc.z - x2.z * ss.z);
            Ks[row][col + 3]  = f2tf32(x1.w * cc.w - x2.w * ss.w);
            Ks[row][col + 32] = f2tf32(x2.x * cc.x + x1.x * ss.x);
            Ks[row][col + 33] = f2tf32(x2.y * cc.y + x1.y * ss.y);
            Ks[row][col + 34] = f2tf32(x2.z * cc.z + x1.z * ss.z);
            Ks[row][col + 35] = f2tf32(x2.w * cc.w + x1.w * ss.w);
        }
        for (int i = tid; i < 64 * 16; i += 128) {
            const int f = i * 4;
            const int row = f >> 6, col = f & 63;
            const float4 vv = ld4h(vg + (size_t)kb * HDIM + f);
            Vs[row][col + 0] = f2tf32(vv.x); Vs[row][col + 1] = f2tf32(vv.y);
            Vs[row][col + 2] = f2tf32(vv.z); Vs[row][col + 3] = f2tf32(vv.w);
        }
        __syncthreads();

        float sacc[8][4] = {};
#pragma unroll
        for (int ks = 0; ks < 8; ks++) {
#pragma unroll
            for (int nt = 0; nt < 8; nt++) {
                uint32_t bk[2];
                bk[0] = Ks[nt * 8 + r4][ks * 8 + c4    ];
                bk[1] = Ks[nt * 8 + r4][ks * 8 + c4 + 4];
                mma16n8k8(sacc[nt], aq[ks], bk);
            }
        }

        float rmax0 = -1e30f, rmax1 = -1e30f;
#pragma unroll
        for (int nt = 0; nt < 8; nt++) {
            const int kj = kb + nt * 8 + 2 * c4;
            if (!((kj     <= qi0) && (kj     + WIN >= qi0))) sacc[nt][0] = -1e30f;
            if (!((kj + 1 <= qi0) && (kj + 1 + WIN >= qi0))) sacc[nt][1] = -1e30f;
            if (!((kj     <= qi1) && (kj     + WIN >= qi1))) sacc[nt][2] = -1e30f;
            if (!((kj + 1 <= qi1) && (kj + 1 + WIN >= qi1))) sacc[nt][3] = -1e30f;
            rmax0 = fmaxf(rmax0, fmaxf(sacc[nt][0], sacc[nt][1]));
            rmax1 = fmaxf(rmax1, fmaxf(sacc[nt][2], sacc[nt][3]));
        }
        rmax0 = fmaxf(rmax0, __shfl_xor_sync(0xffffffffu, rmax0, 1));
        rmax0 = fmaxf(rmax0, __shfl_xor_sync(0xffffffffu, rmax0, 2));
        rmax1 = fmaxf(rmax1, __shfl_xor_sync(0xffffffffu, rmax1, 1));
        rmax1 = fmaxf(rmax1, __shfl_xor_sync(0xffffffffu, rmax1, 2));

        const float mn0 = fmaxf(m2[0], rmax0);
        const float mn1 = fmaxf(m2[1], rmax1);
        const float al0 = __expf(m2[0] - mn0);
        const float al1 = __expf(m2[1] - mn1);
        m2[0] = mn0; m2[1] = mn1;

        float rs0 = 0.f, rs1 = 0.f;
#pragma unroll
        for (int nt = 0; nt < 8; nt++) {
            const float p0 = (sacc[nt][0] > -1e29f) ? __expf(sacc[nt][0] - mn0) : 0.f;
            const float p1 = (sacc[nt][1] > -1e29f) ? __expf(sacc[nt][1] - mn0) : 0.f;
            const float p2 = (sacc[nt][2] > -1e29f) ? __expf(sacc[nt][2] - mn1) : 0.f;
            const float p3 = (sacc[nt][3] > -1e29f) ? __expf(sacc[nt][3] - mn1) : 0.f;
            rs0 += p0 + p1; rs1 += p2 + p3;
            uint2 u01 = make_uint2(f2tf32(p0), f2tf32(p1));
            uint2 u23 = make_uint2(f2tf32(p2), f2tf32(p3));
            *(uint2*)(&Ps[mb + r4    ][nt * 8 + 2 * c4]) = u01;
            *(uint2*)(&Ps[mb + r4 + 8][nt * 8 + 2 * c4]) = u23;
        }
        rs0 += __shfl_xor_sync(0xffffffffu, rs0, 1);
        rs0 += __shfl_xor_sync(0xffffffffu, rs0, 2);
        rs1 += __shfl_xor_sync(0xffffffffu, rs1, 1);
        rs1 += __shfl_xor_sync(0xffffffffu, rs1, 2);
        l2[0] = l2[0] * al0 + rs0;
        l2[1] = l2[1] * al1 + rs1;

#pragma unroll
        for (int dt = 0; dt < 8; dt++) {
            oacc[dt][0] *= al0; oacc[dt][1] *= al0;
            oacc[dt][2] *= al1; oacc[dt][3] *= al1;
        }
        __syncwarp();

#pragma unroll
        for (int ks = 0; ks < 8; ks++) {
            uint32_t ap[4];
            ap[0] = Ps[mb + r4    ][ks * 8 + c4    ];
            ap[1] = Ps[mb + r4 + 8][ks * 8 + c4    ];
            ap[2] = Ps[mb + r4    ][ks * 8 + c4 + 4];
            ap[3] = Ps[mb + r4 + 8][ks * 8 + c4 + 4];
#pragma unroll
            for (int dt = 0; dt < 8; dt++) {
                uint32_t bv[2];
                bv[0] = Vs[ks * 8 + c4    ][dt * 8 + r4];
                bv[1] = Vs[ks * 8 + c4 + 4][dt * 8 + r4];
                mma16n8k8(oacc[dt], ap, bv);
            }
        }
    }

    const float inv0 = 1.0f / l2[0];
    const float inv1 = 1.0f / l2[1];
#pragma unroll
    for (int dt = 0; dt < 8; dt++) {
        const int d = dt * 8 + 2 * c4;
        __half* o0 = g_attn + ((size_t)(b * SEQ + qi0) * HN + h) * HDIM + d;
        __half* o1 = g_attn + ((size_t)(b * SEQ + qi1) * HN + h) * HDIM + d;
        *(__half2*)o0 = __floats2half2_rn(oacc[dt][0] * inv0, oacc[dt][1] * inv0);
        *(__half2*)o1 = __floats2half2_rn(oacc[dt][2] * inv1, oacc[dt][3] * inv1);
    }
}

// ---------------------------------------------------------------------------
extern "C" void kernel_launch(void* const* d_in, const int* in_sizes, int n_in,
                              void* d_out, int out_size)
{
    const float* hs = (const float*)d_in[0];
    const float* Wq = (const float*)d_in[1];
    const float* Wk = (const float*)d_in[2];
    const float* Wv = (const float*)d_in[3];
    const float* Wo = (const float*)d_in[4];
    float* out = (float*)d_out;

    __half* hsh;
    cudaGetSymbolAddress((void**)&hsh, g_hsh);

    build_rope_table<<<(SEQ * 32) / 256, 256>>>();

    // Prep: half operands
    conv_hs<<<(BATCH * SEQ * DM / 4) / 256, 256>>>(hs, hsh);
    transpose_w_h<<<dim3(32, 32, 4), 256>>>(Wq, Wk, Wv, Wo);

    // QKV projections (fp16 m16n8k16 MMA, half outputs with head scatter)
    gemm_qkv<<<dim3(1024 / 128, (BATCH * SEQ) / 128, 3), 256>>>(hsh);

    // Attention (tf32 MMA flash, fused RoPE, half in/out)
    cudaFuncSetAttribute(attn_mma,
                         cudaFuncAttributeMaxDynamicSharedMemorySize,
                         ATTN_SMEM_BYTES);
    attn_mma<<<dim3(SEQ / 64, HN, BATCH), 128, ATTN_SMEM_BYTES>>>();

    // Output projection (fp16 MMA, float output)
    gemm_out<<<dim3(1024 / 128, (BATCH * SEQ) / 128), 256>>>(out);
}

// round 15
// speedup vs baseline: 1.6971x; 1.1435x over previous
#include <cuda_runtime.h>
#include <cuda_fp16.h>
#include <math.h>
#include <stdint.h>

#define HN   16
#define KVN  8
#define HDIM 64
#define WIN  512
#define BATCH 2
#define SEQ  2048
#define DM   1024

// Scratch (half operands for fp16 MMA):
// g_q: [B, HN, S, 64], g_k/g_v: [B, KVN, S, 64] (pre-RoPE, half)
// g_attn: [B*S, HN*64] half; g_hsh: hs half; g_wth: W^T pack half [n][k]
__device__ __half g_q[(size_t)BATCH * HN * SEQ * HDIM];
__device__ __half g_k[(size_t)BATCH * KVN * SEQ * HDIM];
__device__ __half g_v[(size_t)BATCH * KVN * SEQ * HDIM];
__device__ __half g_attn[(size_t)BATCH * SEQ * HN * HDIM];
__device__ __half g_hsh[(size_t)BATCH * SEQ * DM];
#define WT_Q 0
#define WT_K (1024 * 1024)
#define WT_V (1024 * 1024 + 512 * 1024)
#define WT_O (1024 * 1024 + 2 * 512 * 1024)
__device__ __half g_wth[1024 * 1024 + 2 * 512 * 1024 + 1024 * 1024];
__device__ float g_cos[SEQ * 32];
__device__ float g_sin[SEQ * 32];

// ---------------------------------------------------------------------------
__global__ void build_rope_table()
{
    const int idx = blockIdx.x * blockDim.x + threadIdx.x;
    if (idx >= SEQ * 32) return;
    const int p = idx & 31;
    const int s = idx >> 5;
    const double invf = pow(10000.0, -((double)(2 * p)) / 64.0);
    const double ang = (double)s * invf;
    g_cos[idx] = (float)cos(ang);
    g_sin[idx] = (float)sin(ang);
}

// ---------------------------------------------------------------------------
// fp16 m16n8k16, f32 accumulate
__device__ __forceinline__ void mma16n8k16h(float* d, const uint32_t* a,
                                            const uint32_t* b) {
    asm("mma.sync.aligned.m16n8k16.row.col.f32.f16.f16.f32 "
        "{%0,%1,%2,%3}, {%4,%5,%6,%7}, {%8,%9}, {%0,%1,%2,%3};"
        : "+f"(d[0]), "+f"(d[1]), "+f"(d[2]), "+f"(d[3])
        : "r"(a[0]), "r"(a[1]), "r"(a[2]), "r"(a[3]),
          "r"(b[0]), "r"(b[1]));
}

#define CP_ASYNC16(dst_u32, src_ptr) \
    asm volatile("cp.async.ca.shared.global [%0], [%1], 16;" \
                 :: "r"(dst_u32), "l"(src_ptr))
#define CP_COMMIT() asm volatile("cp.async.commit_group;")
#define CP_WAIT(n)  asm volatile("cp.async.wait_group %0;" :: "n"(n))

// ---------------------------------------------------------------------------
// Prep kernels (validated R14)
// ---------------------------------------------------------------------------
__global__ void conv_hs(const float* __restrict__ in, __half* __restrict__ outp)
{
    const int i = blockIdx.x * 256 + threadIdx.x;
    float4 v = ((const float4*)in)[i];
    __half2 h0 = __floats2half2_rn(v.x, v.y);
    __half2 h1 = __floats2half2_rn(v.z, v.w);
    uint2 u;
    u.x = *(uint32_t*)&h0; u.y = *(uint32_t*)&h1;
    *(uint2*)(outp + (size_t)i * 4) = u;
}

__global__ void transpose_w_h(const float* __restrict__ Wq,
                              const float* __restrict__ Wk,
                              const float* __restrict__ Wv,
                              const float* __restrict__ Wo)
{
    const int z = blockIdx.z;
    const float* W; __half* T; int N;
    if (z == 0)      { W = Wq; T = g_wth + WT_Q; N = 1024; }
    else if (z == 1) { W = Wk; T = g_wth + WT_K; N = 512; }
    else if (z == 2) { W = Wv; T = g_wth + WT_V; N = 512; }
    else             { W = Wo; T = g_wth + WT_O; N = 1024; }
    if (blockIdx.x * 32 >= N) return;

    __shared__ float t[32][33];
    const int n0 = blockIdx.x * 32, k0 = blockIdx.y * 32;
    const int tx = threadIdx.x & 31, ty = threadIdx.x >> 5;
#pragma unroll
    for (int r = 0; r < 4; r++)
        t[ty + r * 8][tx] = W[(size_t)(k0 + ty + r * 8) * N + n0 + tx];
    __syncthreads();
#pragma unroll
    for (int r = 0; r < 4; r++)
        T[(size_t)(n0 + ty + r * 8) * 1024 + k0 + tx] = __float2half(t[tx][ty + r * 8]);
}

// ---------------------------------------------------------------------------
// fp16 tensor-core GEMM (validated R14): C = A[M,K]h @ W, BT = W^T [N,K]h.
// BM=BN=128, BK=32, 256 thr, warp tile 64x32 via m16n8k16, double-buffered.
// ---------------------------------------------------------------------------
template <int MODE>
__device__ __forceinline__ void gemm_body(
    const __half* __restrict__ A, const __half* __restrict__ BT,
    void* __restrict__ C, int N, int NH)
{
    __shared__ __half Ah[2][128][40];
    __shared__ __half Bh[2][128][40];

    const int K = DM;
    const int tid  = threadIdx.x;
    const int lane = tid & 31;
    const int wid  = tid >> 5;
    const int wy   = wid >> 2;
    const int wx   = wid & 3;
    const int r4   = lane >> 2;
    const int c4   = lane & 3;
    const int m0   = blockIdx.y * 128, n0 = blockIdx.x * 128;

    const __half* Ab = A + (size_t)m0 * K;
    const __half* Bb = BT + (size_t)n0 * K;

#define GF_FILL(buf, kt) do {                                                 \
    _Pragma("unroll")                                                         \
    for (int i0 = 0; i0 < 2; i0++) {                                          \
        const int i = tid + i0 * 256;                                         \
        const int r = i >> 2, c = (i & 3) * 8;                                \
        CP_ASYNC16((uint32_t)__cvta_generic_to_shared(&Ah[buf][r][c]),        \
                   Ab + (size_t)r * K + (kt) * 32 + c);                       \
        CP_ASYNC16((uint32_t)__cvta_generic_to_shared(&Bh[buf][r][c]),        \
                   Bb + (size_t)r * K + (kt) * 32 + c);                       \
    }                                                                         \
    CP_COMMIT();                                                              \
} while (0)

    GF_FILL(0, 0);

    float acc[4][4][4] = {};
    int buf = 0;
    const int NT = K / 32;

    for (int kt = 0; kt < NT; kt++) {
        if (kt + 1 < NT) {
            GF_FILL(buf ^ 1, kt + 1);
            CP_WAIT(1);
        } else {
            CP_WAIT(0);
        }
        __syncthreads();

#pragma unroll
        for (int ks2 = 0; ks2 < 2; ks2++) {
            const int bw = ks2 * 8;
            uint32_t af[4][4], bf[4][2];
#pragma unroll
            for (int mt = 0; mt < 4; mt++) {
                const int mb = wy * 64 + mt * 16;
                const uint32_t* r0 = (const uint32_t*)&Ah[buf][mb + r4][0];
                const uint32_t* r1 = (const uint32_t*)&Ah[buf][mb + r4 + 8][0];
                af[mt][0] = r0[bw + c4];
                af[mt][1] = r1[bw + c4];
                af[mt][2] = r0[bw + c4 + 4];
                af[mt][3] = r1[bw + c4 + 4];
            }
#pragma unroll
            for (int nt = 0; nt < 4; nt++) {
                const int nb = wx * 32 + nt * 8;
                const uint32_t* rn = (const uint32_t*)&Bh[buf][nb + r4][0];
                bf[nt][0] = rn[bw + c4];
                bf[nt][1] = rn[bw + c4 + 4];
            }
#pragma unroll
            for (int mt = 0; mt < 4; mt++)
#pragma unroll
                for (int nt = 0; nt < 4; nt++)
                    mma16n8k16h(acc[mt][nt], af[mt], bf[nt]);
        }
        __syncthreads();
        buf ^= 1;
    }
#undef GF_FILL

#pragma unroll
    for (int mt = 0; mt < 4; mt++) {
#pragma unroll
        for (int nt = 0; nt < 4; nt++) {
            const int m = m0 + wy * 64 + mt * 16 + r4;
            const int n = n0 + wx * 32 + nt * 8 + 2 * c4;
#pragma unroll
            for (int half_ = 0; half_ < 2; half_++) {
                const int mr = m + half_ * 8;
                const float v0 = acc[mt][nt][half_ * 2];
                const float v1 = acc[mt][nt][half_ * 2 + 1];
                if (MODE == 0) {
                    *(float2*)((float*)C + (size_t)mr * DM + n) =
                        make_float2(v0, v1);
                } else {
                    const int b = mr / SEQ, s = mr % SEQ;
                    const int h = n >> 6, d = n & 63;
                    *(__half2*)((__half*)C +
                        (((size_t)(b * NH + h)) * SEQ + s) * HDIM + d) =
                        __floats2half2_rn(v0, v1);
                }
            }
        }
    }
}

__global__ void __launch_bounds__(256, 2)
gemm_qkv(const __half* __restrict__ hsh)
{
    const int z = blockIdx.z;
    const __half* BT; __half* C; int N, NH;
    if (z == 0)      { BT = g_wth + WT_Q; C = g_q; N = 1024; NH = HN;  }
    else if (z == 1) { BT = g_wth + WT_K; C = g_k; N = 512;  NH = KVN; }
    else             { BT = g_wth + WT_V; C = g_v; N = 512;  NH = KVN; }
    if (blockIdx.x * 128 >= N) return;
    gemm_body<1>(hsh, BT, C, N, NH);
}

__global__ void __launch_bounds__(256, 2)
gemm_out(float* __restrict__ out)
{
    gemm_body<0>(g_attn, g_wth + WT_O, out, 1024, 0);
}

// ---------------------------------------------------------------------------
// fp16 MMA flash attention: 128 threads = 4 warps, one 64-query tile, fused
// RoPE staging. All MMAs m16n8k16 f16 (f32 accum). V staged TRANSPOSED
// (Vt[d][key], key contiguous) so P@V B-fragments are packed half2 words.
// Smem: Ps[64][72]h (Q stage / P), Ks[64][72]h, Vt[64][72]h = 27.6 KB static.
// ---------------------------------------------------------------------------
#define AHS 72

__global__ void __launch_bounds__(128) attn_mma()
{
    __shared__ __half Ps[64][AHS];
    __shared__ __half Ks[64][AHS];
    __shared__ __half Vt[64][AHS];

    const int b = blockIdx.z, h = blockIdx.y;
    const int qb = blockIdx.x * 64;
    const int kvh = h >> 1;            // n_rep = 2
    const int tid  = threadIdx.x;
    const int lane = tid & 31;
    const int wid  = tid >> 5;
    const int mb   = wid * 16;
    const int r4   = lane >> 2;
    const int c4   = lane & 3;

    const __half* qg = g_q + ((size_t)(b * HN + h) * SEQ + qb) * HDIM;
    const __half* kg = g_k + (size_t)(b * KVN + kvh) * SEQ * HDIM;
    const __half* vg = g_v + (size_t)(b * KVN + kvh) * SEQ * HDIM;

    // Stage Q with fused RoPE + 0.125 scale (half out).
    for (int i = tid; i < 64 * 8; i += 128) {
        const int row = i >> 3;
        const int col = (i & 7) * 4;
        uint2 u1 = *(const uint2*)(qg + row * HDIM + col);
        uint2 u2 = *(const uint2*)(qg + row * HDIM + col + 32);
        float2 a0 = __half22float2(*(__half2*)&u1.x);
        float2 a1 = __half22float2(*(__half2*)&u1.y);
        float2 b0 = __half22float2(*(__half2*)&u2.x);
        float2 b1 = __half22float2(*(__half2*)&u2.y);
        const float4 cc = *(const float4*)(&g_cos[(qb + row) * 32 + col]);
        const float4 ss = *(const float4*)(&g_sin[(qb + row) * 32 + col]);
        *(__half2*)&Ps[row][col] = __floats2half2_rn(
            (a0.x * cc.x - b0.x * ss.x) * 0.125f,
            (a0.y * cc.y - b0.y * ss.y) * 0.125f);
        *(__half2*)&Ps[row][col + 2] = __floats2half2_rn(
            (a1.x * cc.z - b1.x * ss.z) * 0.125f,
            (a1.y * cc.w - b1.y * ss.w) * 0.125f);
        *(__half2*)&Ps[row][col + 32] = __floats2half2_rn(
            (b0.x * cc.x + a0.x * ss.x) * 0.125f,
            (b0.y * cc.y + a0.y * ss.y) * 0.125f);
        *(__half2*)&Ps[row][col + 34] = __floats2half2_rn(
            (b1.x * cc.z + a1.x * ss.z) * 0.125f,
            (b1.y * cc.w + a1.y * ss.w) * 0.125f);
    }
    __syncthreads();

    // Q fragments for m16n8k16: aq[ks] = k-dims ks*16..ks*16+15.
    uint32_t aq[4][4];
#pragma unroll
    for (int ks = 0; ks < 4; ks++) {
        const uint32_t* r0 = (const uint32_t*)&Ps[mb + r4][0];
        const uint32_t* r1 = (const uint32_t*)&Ps[mb + r4 + 8][0];
        aq[ks][0] = r0[ks * 8 + c4];
        aq[ks][1] = r1[ks * 8 + c4];
        aq[ks][2] = r0[ks * 8 + c4 + 4];
        aq[ks][3] = r1[ks * 8 + c4 + 4];
    }

    float oacc[8][4] = {};
    float m2[2] = {-1e30f, -1e30f};
    float l2[2] = {0.0f, 0.0f};
    const int qi0 = qb + mb + r4;
    const int qi1 = qi0 + 8;

    const int kstart = (qb >= WIN) ? (qb - WIN) : 0;

    for (int kb = kstart; kb <= qb; kb += 64) {
        __syncthreads();
        // K staging with fused RoPE (half out).
        for (int i = tid; i < 64 * 8; i += 128) {
            const int row = i >> 3;
            const int col = (i & 7) * 4;
            uint2 u1 = *(const uint2*)(kg + (size_t)(kb + row) * HDIM + col);
            uint2 u2 = *(const uint2*)(kg + (size_t)(kb + row) * HDIM + col + 32);
            float2 a0 = __half22float2(*(__half2*)&u1.x);
            float2 a1 = __half22float2(*(__half2*)&u1.y);
            float2 b0 = __half22float2(*(__half2*)&u2.x);
            float2 b1 = __half22float2(*(__half2*)&u2.y);
            const float4 cc = *(const float4*)(&g_cos[(kb + row) * 32 + col]);
            const float4 ss = *(const float4*)(&g_sin[(kb + row) * 32 + col]);
            *(__half2*)&Ks[row][col] = __floats2half2_rn(
                a0.x * cc.x - b0.x * ss.x, a0.y * cc.y - b0.y * ss.y);
            *(__half2*)&Ks[row][col + 2] = __floats2half2_rn(
                a1.x * cc.z - b1.x * ss.z, a1.y * cc.w - b1.y * ss.w);
            *(__half2*)&Ks[row][col + 32] = __floats2half2_rn(
                b0.x * cc.x + a0.x * ss.x, b0.y * cc.y + a0.y * ss.y);
            *(__half2*)&Ks[row][col + 34] = __floats2half2_rn(
                b1.x * cc.z + a1.x * ss.z, b1.y * cc.w + a1.y * ss.w);
        }
        // V staged transposed: Vt[d][key], key-pairs packed as half2.
        for (int i = tid; i < 32 * 8; i += 128) {
            const int kp = i & 31;        // key pair 0..31
            const int dg = i >> 5;        // d group 0..7 (8 d's each)
            const __half* v0 = vg + (size_t)(kb + 2 * kp) * HDIM + dg * 8;
            const __half* v1 = v0 + HDIM;
            uint4 ua = *(const uint4*)v0;
            uint4 ub = *(const uint4*)v1;
            const __half* ah = (const __half*)&ua;
            const __half* bh = (const __half*)&ub;
#pragma unroll
            for (int j = 0; j < 8; j++)
                *(__half2*)&Vt[dg * 8 + j][2 * kp] = __halves2half2(ah[j], bh[j]);
        }
        __syncthreads();

        // ---- S = Q @ K^T (fp16 k16) ----
        float sacc[8][4] = {};
#pragma unroll
        for (int ks = 0; ks < 4; ks++) {
#pragma unroll
            for (int nt = 0; nt < 8; nt++) {
                const uint32_t* rn = (const uint32_t*)&Ks[nt * 8 + r4][0];
                uint32_t bk[2];
                bk[0] = rn[ks * 8 + c4];
                bk[1] = rn[ks * 8 + c4 + 4];
                mma16n8k16h(sacc[nt], aq[ks], bk);
            }
        }

        // ---- mask + row max ----
        float rmax0 = -1e30f, rmax1 = -1e30f;
#pragma unroll
        for (int nt = 0; nt < 8; nt++) {
            const int kj = kb + nt * 8 + 2 * c4;
            if (!((kj     <= qi0) && (kj     + WIN >= qi0))) sacc[nt][0] = -1e30f;
            if (!((kj + 1 <= qi0) && (kj + 1 + WIN >= qi0))) sacc[nt][1] = -1e30f;
            if (!((kj     <= qi1) && (kj     + WIN >= qi1))) sacc[nt][2] = -1e30f;
            if (!((kj + 1 <= qi1) && (kj + 1 + WIN >= qi1))) sacc[nt][3] = -1e30f;
            rmax0 = fmaxf(rmax0, fmaxf(sacc[nt][0], sacc[nt][1]));
            rmax1 = fmaxf(rmax1, fmaxf(sacc[nt][2], sacc[nt][3]));
        }
        rmax0 = fmaxf(rmax0, __shfl_xor_sync(0xffffffffu, rmax0, 1));
        rmax0 = fmaxf(rmax0, __shfl_xor_sync(0xffffffffu, rmax0, 2));
        rmax1 = fmaxf(rmax1, __shfl_xor_sync(0xffffffffu, rmax1, 1));
        rmax1 = fmaxf(rmax1, __shfl_xor_sync(0xffffffffu, rmax1, 2));

        const float mn0 = fmaxf(m2[0], rmax0);
        const float mn1 = fmaxf(m2[1], rmax1);
        const float al0 = __expf(m2[0] - mn0);
        const float al1 = __expf(m2[1] - mn1);
        m2[0] = mn0; m2[1] = mn1;

        // ---- P = exp(S - m), store half2, row sums ----
        float rs0 = 0.f, rs1 = 0.f;
#pragma unroll
        for (int nt = 0; nt < 8; nt++) {
            const float p0 = (sacc[nt][0] > -1e29f) ? __expf(sacc[nt][0] - mn0) : 0.f;
            const float p1 = (sacc[nt][1] > -1e29f) ? __expf(sacc[nt][1] - mn0) : 0.f;
            const float p2 = (sacc[nt][2] > -1e29f) ? __expf(sacc[nt][2] - mn1) : 0.f;
            const float p3 = (sacc[nt][3] > -1e29f) ? __expf(sacc[nt][3] - mn1) : 0.f;
            rs0 += p0 + p1; rs1 += p2 + p3;
            *(__half2*)&Ps[mb + r4    ][nt * 8 + 2 * c4] = __floats2half2_rn(p0, p1);
            *(__half2*)&Ps[mb + r4 + 8][nt * 8 + 2 * c4] = __floats2half2_rn(p2, p3);
        }
        rs0 += __shfl_xor_sync(0xffffffffu, rs0, 1);
        rs0 += __shfl_xor_sync(0xffffffffu, rs0, 2);
        rs1 += __shfl_xor_sync(0xffffffffu, rs1, 1);
        rs1 += __shfl_xor_sync(0xffffffffu, rs1, 2);
        l2[0] = l2[0] * al0 + rs0;
        l2[1] = l2[1] * al1 + rs1;

#pragma unroll
        for (int dt = 0; dt < 8; dt++) {
            oacc[dt][0] *= al0; oacc[dt][1] *= al0;
            oacc[dt][2] *= al1; oacc[dt][3] *= al1;
        }
        __syncwarp();   // P stores visible to this warp's fragment loads

        // ---- O += P @ V (fp16 k16; B from Vt[d][key]) ----
#pragma unroll
        for (int ks = 0; ks < 4; ks++) {
            const uint32_t* p0 = (const uint32_t*)&Ps[mb + r4][0];
            const uint32_t* p1 = (const uint32_t*)&Ps[mb + r4 + 8][0];
            uint32_t ap[4];
            ap[0] = p0[ks * 8 + c4];
            ap[1] = p1[ks * 8 + c4];
            ap[2] = p0[ks * 8 + c4 + 4];
            ap[3] = p1[ks * 8 + c4 + 4];
#pragma unroll
            for (int dt = 0; dt < 8; dt++) {
                const uint32_t* rv = (const uint32_t*)&Vt[dt * 8 + r4][0];
                uint32_t bv[2];
                bv[0] = rv[ks * 8 + c4];
                bv[1] = rv[ks * 8 + c4 + 4];
                mma16n8k16h(oacc[dt], ap, bv);
            }
        }
    }

    // ---- epilogue: normalize, write half to g_attn [B*S, HN*64] ----
    const float inv0 = 1.0f / l2[0];
    const float inv1 = 1.0f / l2[1];
#pragma unroll
    for (int dt = 0; dt < 8; dt++) {
        const int d = dt * 8 + 2 * c4;
        __half* o0 = g_attn + ((size_t)(b * SEQ + qi0) * HN + h) * HDIM + d;
        __half* o1 = g_attn + ((size_t)(b * SEQ + qi1) * HN + h) * HDIM + d;
        *(__half2*)o0 = __floats2half2_rn(oacc[dt][0] * inv0, oacc[dt][1] * inv0);
        *(__half2*)o1 = __floats2half2_rn(oacc[dt][2] * inv1, oacc[dt][3] * inv1);
    }
}

// ---------------------------------------------------------------------------
extern "C" void kernel_launch(void* const* d_in, const int* in_sizes, int n_in,
                              void* d_out, int out_size)
{
    const float* hs = (const float*)d_in[0];
    const float* Wq = (const float*)d_in[1];
    const float* Wk = (const float*)d_in[2];
    const float* Wv = (const float*)d_in[3];
    const float* Wo = (const float*)d_in[4];
    float* out = (float*)d_out;

    __half* hsh;
    cudaGetSymbolAddress((void**)&hsh, g_hsh);

    build_rope_table<<<(SEQ * 32) / 256, 256>>>();

    // Prep: half operands
    conv_hs<<<(BATCH * SEQ * DM / 4) / 256, 256>>>(hs, hsh);
    transpose_w_h<<<dim3(32, 32, 4), 256>>>(Wq, Wk, Wv, Wo);

    // QKV projections (fp16 m16n8k16 MMA, half outputs with head scatter)
    gemm_qkv<<<dim3(1024 / 128, (BATCH * SEQ) / 128, 3), 256>>>(hsh);

    // Attention (fp16 m16n8k16 MMA flash, fused RoPE)
    attn_mma<<<dim3(SEQ / 64, HN, BATCH), 128>>>();

    // Output projection (fp16 MMA, float output)
    gemm_out<<<dim3(1024 / 128, (BATCH * SEQ) / 128), 256>>>(out);
}

// round 16
// speedup vs baseline: 1.7528x; 1.0328x over previous
#include <cuda_runtime.h>
#include <cuda_fp16.h>
#include <math.h>
#include <stdint.h>

#define HN   16
#define KVN  8
#define HDIM 64
#define WIN  512
#define BATCH 2
#define SEQ  2048
#define DM   1024

// Scratch (half operands for fp16 MMA):
__device__ __half g_q[(size_t)BATCH * HN * SEQ * HDIM];
__device__ __half g_k[(size_t)BATCH * KVN * SEQ * HDIM];
__device__ __half g_v[(size_t)BATCH * KVN * SEQ * HDIM];
__device__ __half g_attn[(size_t)BATCH * SEQ * HN * HDIM];
__device__ __half g_hsh[(size_t)BATCH * SEQ * DM];
#define WT_Q 0
#define WT_K (1024 * 1024)
#define WT_V (1024 * 1024 + 512 * 1024)
#define WT_O (1024 * 1024 + 2 * 512 * 1024)
__device__ __half g_wth[1024 * 1024 + 2 * 512 * 1024 + 1024 * 1024];
__device__ float g_cos[SEQ * 32];
__device__ float g_sin[SEQ * 32];

// ---------------------------------------------------------------------------
__global__ void build_rope_table()
{
    const int idx = blockIdx.x * blockDim.x + threadIdx.x;
    if (idx >= SEQ * 32) return;
    const int p = idx & 31;
    const int s = idx >> 5;
    const double invf = pow(10000.0, -((double)(2 * p)) / 64.0);
    const double ang = (double)s * invf;
    g_cos[idx] = (float)cos(ang);
    g_sin[idx] = (float)sin(ang);
}

// ---------------------------------------------------------------------------
__device__ __forceinline__ void mma16n8k16h(float* d, const uint32_t* a,
                                            const uint32_t* b) {
    asm("mma.sync.aligned.m16n8k16.row.col.f32.f16.f16.f32 "
        "{%0,%1,%2,%3}, {%4,%5,%6,%7}, {%8,%9}, {%0,%1,%2,%3};"
        : "+f"(d[0]), "+f"(d[1]), "+f"(d[2]), "+f"(d[3])
        : "r"(a[0]), "r"(a[1]), "r"(a[2]), "r"(a[3]),
          "r"(b[0]), "r"(b[1]));
}

#define CP_ASYNC16(dst_u32, src_ptr) \
    asm volatile("cp.async.ca.shared.global [%0], [%1], 16;" \
                 :: "r"(dst_u32), "l"(src_ptr))
#define CP_COMMIT() asm volatile("cp.async.commit_group;")
#define CP_WAIT(n)  asm volatile("cp.async.wait_group %0;" :: "n"(n))

// ---------------------------------------------------------------------------
// Prep kernels (validated R14/R15)
// ---------------------------------------------------------------------------
__global__ void conv_hs(const float* __restrict__ in, __half* __restrict__ outp)
{
    const int i = blockIdx.x * 256 + threadIdx.x;
    float4 v = ((const float4*)in)[i];
    __half2 h0 = __floats2half2_rn(v.x, v.y);
    __half2 h1 = __floats2half2_rn(v.z, v.w);
    uint2 u;
    u.x = *(uint32_t*)&h0; u.y = *(uint32_t*)&h1;
    *(uint2*)(outp + (size_t)i * 4) = u;
}

__global__ void transpose_w_h(const float* __restrict__ Wq,
                              const float* __restrict__ Wk,
                              const float* __restrict__ Wv,
                              const float* __restrict__ Wo)
{
    const int z = blockIdx.z;
    const float* W; __half* T; int N;
    if (z == 0)      { W = Wq; T = g_wth + WT_Q; N = 1024; }
    else if (z == 1) { W = Wk; T = g_wth + WT_K; N = 512; }
    else if (z == 2) { W = Wv; T = g_wth + WT_V; N = 512; }
    else             { W = Wo; T = g_wth + WT_O; N = 1024; }
    if (blockIdx.x * 32 >= N) return;

    __shared__ float t[32][33];
    const int n0 = blockIdx.x * 32, k0 = blockIdx.y * 32;
    const int tx = threadIdx.x & 31, ty = threadIdx.x >> 5;
#pragma unroll
    for (int r = 0; r < 4; r++)
        t[ty + r * 8][tx] = W[(size_t)(k0 + ty + r * 8) * N + n0 + tx];
    __syncthreads();
#pragma unroll
    for (int r = 0; r < 4; r++)
        T[(size_t)(n0 + ty + r * 8) * 1024 + k0 + tx] = __float2half(t[tx][ty + r * 8]);
}

// ---------------------------------------------------------------------------
// fp16 tensor-core GEMM, 3-stage cp.async ring, ONE __syncthreads per k-tile.
// C = A[M,K]h @ W, BT = W^T [N,K]h. BM=BN=128, BK=32, 256 thr, warp 64x32.
// Dynamic smem: 3 stages x (Ah[128][40] + Bh[128][40]) halves = 61,440 B.
// MODE 0: float C linear (N=1024). MODE 1: half C scatter [B,NH,S,64].
// ---------------------------------------------------------------------------
#define GEMM_SMEM_BYTES (3 * 2 * 128 * 40 * 2)

template <int MODE>
__device__ __forceinline__ void gemm_body(
    const __half* __restrict__ A, const __half* __restrict__ BT,
    void* __restrict__ C, int N, int NH)
{
    extern __shared__ __half hsm[];
    __half (*Ah)[128][40] = (__half(*)[128][40])(hsm);
    __half (*Bh)[128][40] = (__half(*)[128][40])(hsm + 3 * 128 * 40);

    const int K = DM;
    const int tid  = threadIdx.x;
    const int lane = tid & 31;
    const int wid  = tid >> 5;
    const int wy   = wid >> 2;
    const int wx   = wid & 3;
    const int r4   = lane >> 2;
    const int c4   = lane & 3;
    const int m0   = blockIdx.y * 128, n0 = blockIdx.x * 128;

    const __half* Ab = A + (size_t)m0 * K;
    const __half* Bb = BT + (size_t)n0 * K;

#define GF_FILL(st, kt) do {                                                  \
    _Pragma("unroll")                                                         \
    for (int i0 = 0; i0 < 2; i0++) {                                          \
        const int i = tid + i0 * 256;                                         \
        const int r = i >> 2, c = (i & 3) * 8;                                \
        CP_ASYNC16((uint32_t)__cvta_generic_to_shared(&Ah[st][r][c]),         \
                   Ab + (size_t)r * K + (kt) * 32 + c);                       \
        CP_ASYNC16((uint32_t)__cvta_generic_to_shared(&Bh[st][r][c]),         \
                   Bb + (size_t)r * K + (kt) * 32 + c);                       \
    }                                                                         \
    CP_COMMIT();                                                              \
} while (0)

    const int NT = K / 32;   // 32
    GF_FILL(0, 0);
    GF_FILL(1, 1);

    float acc[4][4][4] = {};

    for (int kt = 0; kt < NT; kt++) {
        const int st = kt % 3;
        if (kt + 1 < NT) { CP_WAIT(1); } else { CP_WAIT(0); }
        __syncthreads();   // stage st ready for all; all warps done with st-1 reads

#pragma unroll
        for (int ks2 = 0; ks2 < 2; ks2++) {
            const int bw = ks2 * 8;
            uint32_t af[4][4], bf[4][2];
#pragma unroll
            for (int mt = 0; mt < 4; mt++) {
                const int mb = wy * 64 + mt * 16;
                const uint32_t* r0 = (const uint32_t*)&Ah[st][mb + r4][0];
                const uint32_t* r1 = (const uint32_t*)&Ah[st][mb + r4 + 8][0];
                af[mt][0] = r0[bw + c4];
                af[mt][1] = r1[bw + c4];
                af[mt][2] = r0[bw + c4 + 4];
                af[mt][3] = r1[bw + c4 + 4];
            }
#pragma unroll
            for (int nt = 0; nt < 4; nt++) {
                const int nb = wx * 32 + nt * 8;
                const uint32_t* rn = (const uint32_t*)&Bh[st][nb + r4][0];
                bf[nt][0] = rn[bw + c4];
                bf[nt][1] = rn[bw + c4 + 4];
            }
#pragma unroll
            for (int mt = 0; mt < 4; mt++)
#pragma unroll
                for (int nt = 0; nt < 4; nt++)
                    mma16n8k16h(acc[mt][nt], af[mt], bf[nt]);
        }

        if (kt + 2 < NT) GF_FILL((kt + 2) % 3, kt + 2);
    }
#undef GF_FILL

#pragma unroll
    for (int mt = 0; mt < 4; mt++) {
#pragma unroll
        for (int nt = 0; nt < 4; nt++) {
            const int m = m0 + wy * 64 + mt * 16 + r4;
            const int n = n0 + wx * 32 + nt * 8 + 2 * c4;
#pragma unroll
            for (int half_ = 0; half_ < 2; half_++) {
                const int mr = m + half_ * 8;
                const float v0 = acc[mt][nt][half_ * 2];
                const float v1 = acc[mt][nt][half_ * 2 + 1];
                if (MODE == 0) {
                    *(float2*)((float*)C + (size_t)mr * DM + n) =
                        make_float2(v0, v1);
                } else {
                    const int b = mr / SEQ, s = mr % SEQ;
                    const int h = n >> 6, d = n & 63;
                    *(__half2*)((__half*)C +
                        (((size_t)(b * NH + h)) * SEQ + s) * HDIM + d) =
                        __floats2half2_rn(v0, v1);
                }
            }
        }
    }
}

__global__ void __launch_bounds__(256, 2)
gemm_qkv(const __half* __restrict__ hsh)
{
    const int z = blockIdx.z;
    const __half* BT; __half* C; int N, NH;
    if (z == 0)      { BT = g_wth + WT_Q; C = g_q; N = 1024; NH = HN;  }
    else if (z == 1) { BT = g_wth + WT_K; C = g_k; N = 512;  NH = KVN; }
    else             { BT = g_wth + WT_V; C = g_v; N = 512;  NH = KVN; }
    if (blockIdx.x * 128 >= N) return;
    gemm_body<1>(hsh, BT, C, N, NH);
}

__global__ void __launch_bounds__(256, 2)
gemm_out(float* __restrict__ out)
{
    gemm_body<0>(g_attn, g_wth + WT_O, out, 1024, 0);
}

// ---------------------------------------------------------------------------
// fp16 MMA flash attention (validated R15): 128 thr = 4 warps, 64-q tile,
// fused RoPE staging, V staged transposed, all MMAs m16n8k16.
// ---------------------------------------------------------------------------
#define AHS 72

__global__ void __launch_bounds__(128) attn_mma()
{
    __shared__ __half Ps[64][AHS];
    __shared__ __half Ks[64][AHS];
    __shared__ __half Vt[64][AHS];

    const int b = blockIdx.z, h = blockIdx.y;
    const int qb = blockIdx.x * 64;
    const int kvh = h >> 1;
    const int tid  = threadIdx.x;
    const int lane = tid & 31;
    const int wid  = tid >> 5;
    const int mb   = wid * 16;
    const int r4   = lane >> 2;
    const int c4   = lane & 3;

    const __half* qg = g_q + ((size_t)(b * HN + h) * SEQ + qb) * HDIM;
    const __half* kg = g_k + (size_t)(b * KVN + kvh) * SEQ * HDIM;
    const __half* vg = g_v + (size_t)(b * KVN + kvh) * SEQ * HDIM;

    for (int i = tid; i < 64 * 8; i += 128) {
        const int row = i >> 3;
        const int col = (i & 7) * 4;
        uint2 u1 = *(const uint2*)(qg + row * HDIM + col);
        uint2 u2 = *(const uint2*)(qg + row * HDIM + col + 32);
        float2 a0 = __half22float2(*(__half2*)&u1.x);
        float2 a1 = __half22float2(*(__half2*)&u1.y);
        float2 b0 = __half22float2(*(__half2*)&u2.x);
        float2 b1 = __half22float2(*(__half2*)&u2.y);
        const float4 cc = *(const float4*)(&g_cos[(qb + row) * 32 + col]);
        const float4 ss = *(const float4*)(&g_sin[(qb + row) * 32 + col]);
        *(__half2*)&Ps[row][col] = __floats2half2_rn(
            (a0.x * cc.x - b0.x * ss.x) * 0.125f,
            (a0.y * cc.y - b0.y * ss.y) * 0.125f);
        *(__half2*)&Ps[row][col + 2] = __floats2half2_rn(
            (a1.x * cc.z - b1.x * ss.z) * 0.125f,
            (a1.y * cc.w - b1.y * ss.w) * 0.125f);
        *(__half2*)&Ps[row][col + 32] = __floats2half2_rn(
            (b0.x * cc.x + a0.x * ss.x) * 0.125f,
            (b0.y * cc.y + a0.y * ss.y) * 0.125f);
        *(__half2*)&Ps[row][col + 34] = __floats2half2_rn(
            (b1.x * cc.z + a1.x * ss.z) * 0.125f,
            (b1.y * cc.w + a1.y * ss.w) * 0.125f);
    }
    __syncthreads();

    uint32_t aq[4][4];
#pragma unroll
    for (int ks = 0; ks < 4; ks++) {
        const uint32_t* r0 = (const uint32_t*)&Ps[mb + r4][0];
        const uint32_t* r1 = (const uint32_t*)&Ps[mb + r4 + 8][0];
        aq[ks][0] = r0[ks * 8 + c4];
        aq[ks][1] = r1[ks * 8 + c4];
        aq[ks][2] = r0[ks * 8 + c4 + 4];
        aq[ks][3] = r1[ks * 8 + c4 + 4];
    }

    float oacc[8][4] = {};
    float m2[2] = {-1e30f, -1e30f};
    float l2[2] = {0.0f, 0.0f};
    const int qi0 = qb + mb + r4;
    const int qi1 = qi0 + 8;

    const int kstart = (qb >= WIN) ? (qb - WIN) : 0;

    for (int kb = kstart; kb <= qb; kb += 64) {
        __syncthreads();
        for (int i = tid; i < 64 * 8; i += 128) {
            const int row = i >> 3;
            const int col = (i & 7) * 4;
            uint2 u1 = *(const uint2*)(kg + (size_t)(kb + row) * HDIM + col);
            uint2 u2 = *(const uint2*)(kg + (size_t)(kb + row) * HDIM + col + 32);
            float2 a0 = __half22float2(*(__half2*)&u1.x);
            float2 a1 = __half22float2(*(__half2*)&u1.y);
            float2 b0 = __half22float2(*(__half2*)&u2.x);
            float2 b1 = __half22float2(*(__half2*)&u2.y);
            const float4 cc = *(const float4*)(&g_cos[(kb + row) * 32 + col]);
            const float4 ss = *(const float4*)(&g_sin[(kb + row) * 32 + col]);
            *(__half2*)&Ks[row][col] = __floats2half2_rn(
                a0.x * cc.x - b0.x * ss.x, a0.y * cc.y - b0.y * ss.y);
            *(__half2*)&Ks[row][col + 2] = __floats2half2_rn(
                a1.x * cc.z - b1.x * ss.z, a1.y * cc.w - b1.y * ss.w);
            *(__half2*)&Ks[row][col + 32] = __floats2half2_rn(
                b0.x * cc.x + a0.x * ss.x, b0.y * cc.y + a0.y * ss.y);
            *(__half2*)&Ks[row][col + 34] = __floats2half2_rn(
                b1.x * cc.z + a1.x * ss.z, b1.y * cc.w + a1.y * ss.w);
        }
        for (int i = tid; i < 32 * 8; i += 128) {
            const int kp = i & 31;
            const int dg = i >> 5;
            const __half* v0 = vg + (size_t)(kb + 2 * kp) * HDIM + dg * 8;
            const __half* v1 = v0 + HDIM;
            uint4 ua = *(const uint4*)v0;
            uint4 ub = *(const uint4*)v1;
            const __half* ah = (const __half*)&ua;
            const __half* bh = (const __half*)&ub;
#pragma unroll
            for (int j = 0; j < 8; j++)
                *(__half2*)&Vt[dg * 8 + j][2 * kp] = __halves2half2(ah[j], bh[j]);
        }
        __syncthreads();

        float sacc[8][4] = {};
#pragma unroll
        for (int ks = 0; ks < 4; ks++) {
#pragma unroll
            for (int nt = 0; nt < 8; nt++) {
                const uint32_t* rn = (const uint32_t*)&Ks[nt * 8 + r4][0];
                uint32_t bk[2];
                bk[0] = rn[ks * 8 + c4];
                bk[1] = rn[ks * 8 + c4 + 4];
                mma16n8k16h(sacc[nt], aq[ks], bk);
            }
        }

        float rmax0 = -1e30f, rmax1 = -1e30f;
#pragma unroll
        for (int nt = 0; nt < 8; nt++) {
            const int kj = kb + nt * 8 + 2 * c4;
            if (!((kj     <= qi0) && (kj     + WIN >= qi0))) sacc[nt][0] = -1e30f;
            if (!((kj + 1 <= qi0) && (kj + 1 + WIN >= qi0))) sacc[nt][1] = -1e30f;
            if (!((kj     <= qi1) && (kj     + WIN >= qi1))) sacc[nt][2] = -1e30f;
            if (!((kj + 1 <= qi1) && (kj + 1 + WIN >= qi1))) sacc[nt][3] = -1e30f;
            rmax0 = fmaxf(rmax0, fmaxf(sacc[nt][0], sacc[nt][1]));
            rmax1 = fmaxf(rmax1, fmaxf(sacc[nt][2], sacc[nt][3]));
        }
        rmax0 = fmaxf(rmax0, __shfl_xor_sync(0xffffffffu, rmax0, 1));
        rmax0 = fmaxf(rmax0, __shfl_xor_sync(0xffffffffu, rmax0, 2));
        rmax1 = fmaxf(rmax1, __shfl_xor_sync(0xffffffffu, rmax1, 1));
        rmax1 = fmaxf(rmax1, __shfl_xor_sync(0xffffffffu, rmax1, 2));

        const float mn0 = fmaxf(m2[0], rmax0);
        const float mn1 = fmaxf(m2[1], rmax1);
        const float al0 = __expf(m2[0] - mn0);
        const float al1 = __expf(m2[1] - mn1);
        m2[0] = mn0; m2[1] = mn1;

        float rs0 = 0.f, rs1 = 0.f;
#pragma unroll
        for (int nt = 0; nt < 8; nt++) {
            const float p0 = (sacc[nt][0] > -1e29f) ? __expf(sacc[nt][0] - mn0) : 0.f;
            const float p1 = (sacc[nt][1] > -1e29f) ? __expf(sacc[nt][1] - mn0) : 0.f;
            const float p2 = (sacc[nt][2] > -1e29f) ? __expf(sacc[nt][2] - mn1) : 0.f;
            const float p3 = (sacc[nt][3] > -1e29f) ? __expf(sacc[nt][3] - mn1) : 0.f;
            rs0 += p0 + p1; rs1 += p2 + p3;
            *(__half2*)&Ps[mb + r4    ][nt * 8 + 2 * c4] = __floats2half2_rn(p0, p1);
            *(__half2*)&Ps[mb + r4 + 8][nt * 8 + 2 * c4] = __floats2half2_rn(p2, p3);
        }
        rs0 += __shfl_xor_sync(0xffffffffu, rs0, 1);
        rs0 += __shfl_xor_sync(0xffffffffu, rs0, 2);
        rs1 += __shfl_xor_sync(0xffffffffu, rs1, 1);
        rs1 += __shfl_xor_sync(0xffffffffu, rs1, 2);
        l2[0] = l2[0] * al0 + rs0;
        l2[1] = l2[1] * al1 + rs1;

#pragma unroll
        for (int dt = 0; dt < 8; dt++) {
            oacc[dt][0] *= al0; oacc[dt][1] *= al0;
            oacc[dt][2] *= al1; oacc[dt][3] *= al1;
        }
        __syncwarp();

#pragma unroll
        for (int ks = 0; ks < 4; ks++) {
            const uint32_t* p0 = (const uint32_t*)&Ps[mb + r4][0];
            const uint32_t* p1 = (const uint32_t*)&Ps[mb + r4 + 8][0];
            uint32_t ap[4];
            ap[0] = p0[ks * 8 + c4];
            ap[1] = p1[ks * 8 + c4];
            ap[2] = p0[ks * 8 + c4 + 4];
            ap[3] = p1[ks * 8 + c4 + 4];
#pragma unroll
            for (int dt = 0; dt < 8; dt++) {
                const uint32_t* rv = (const uint32_t*)&Vt[dt * 8 + r4][0];
                uint32_t bv[2];
                bv[0] = rv[ks * 8 + c4];
                bv[1] = rv[ks * 8 + c4 + 4];
                mma16n8k16h(oacc[dt], ap, bv);
            }
        }
    }

    const float inv0 = 1.0f / l2[0];
    const float inv1 = 1.0f / l2[1];
#pragma unroll
    for (int dt = 0; dt < 8; dt++) {
        const int d = dt * 8 + 2 * c4;
        __half* o0 = g_attn + ((size_t)(b * SEQ + qi0) * HN + h) * HDIM + d;
        __half* o1 = g_attn + ((size_t)(b * SEQ + qi1) * HN + h) * HDIM + d;
        *(__half2*)o0 = __floats2half2_rn(oacc[dt][0] * inv0, oacc[dt][1] * inv0);
        *(__half2*)o1 = __floats2half2_rn(oacc[dt][2] * inv1, oacc[dt][3] * inv1);
    }
}

// ---------------------------------------------------------------------------
extern "C" void kernel_launch(void* const* d_in, const int* in_sizes, int n_in,
                              void* d_out, int out_size)
{
    const float* hs = (const float*)d_in[0];
    const float* Wq = (const float*)d_in[1];
    const float* Wk = (const float*)d_in[2];
    const float* Wv = (const float*)d_in[3];
    const float* Wo = (const float*)d_in[4];
    float* out = (float*)d_out;

    __half* hsh;
    cudaGetSymbolAddress((void**)&hsh, g_hsh);

    build_rope_table<<<(SEQ * 32) / 256, 256>>>();

    // Prep: half operands
    conv_hs<<<(BATCH * SEQ * DM / 4) / 256, 256>>>(hs, hsh);
    transpose_w_h<<<dim3(32, 32, 4), 256>>>(Wq, Wk, Wv, Wo);

    cudaFuncSetAttribute(gemm_qkv,
                         cudaFuncAttributeMaxDynamicSharedMemorySize,
                         GEMM_SMEM_BYTES);
    cudaFuncSetAttribute(gemm_out,
                         cudaFuncAttributeMaxDynamicSharedMemorySize,
                         GEMM_SMEM_BYTES);

    // QKV projections (fp16 MMA, 3-stage pipeline)
    gemm_qkv<<<dim3(1024 / 128, (BATCH * SEQ) / 128, 3), 256,
               GEMM_SMEM_BYTES>>>(hsh);

    // Attention (fp16 MMA flash, fused RoPE)
    attn_mma<<<dim3(SEQ / 64, HN, BATCH), 128>>>();

    // Output projection (fp16 MMA, float output)
    gemm_out<<<dim3(1024 / 128, (BATCH * SEQ) / 128), 256,
               GEMM_SMEM_BYTES>>>(out);
}

// round 17
// speedup vs baseline: 1.9347x; 1.1038x over previous
#include <cuda_runtime.h>
#include <cuda_fp16.h>
#include <math.h>
#include <stdint.h>

#define HN   16
#define KVN  8
#define HDIM 64
#define WIN  512
#define BATCH 2
#define SEQ  2048
#define DM   1024

// Scratch (half operands for fp16 MMA):
__device__ __half g_q[(size_t)BATCH * HN * SEQ * HDIM];
__device__ __half g_k[(size_t)BATCH * KVN * SEQ * HDIM];
__device__ __half g_v[(size_t)BATCH * KVN * SEQ * HDIM];
__device__ __half g_attn[(size_t)BATCH * SEQ * HN * HDIM];
__device__ __half g_hsh[(size_t)BATCH * SEQ * DM];
#define WT_Q 0
#define WT_K (1024 * 1024)
#define WT_V (1024 * 1024 + 512 * 1024)
#define WT_O (1024 * 1024 + 2 * 512 * 1024)
__device__ __half g_wth[1024 * 1024 + 2 * 512 * 1024 + 1024 * 1024];
__device__ float g_cos[SEQ * 32];
__device__ float g_sin[SEQ * 32];
// RoPE anchor tables: per freq p: hi (32 entries: angle = hi*64*invf),
// lo (64 entries: angle = lo*invf). Double-precision trig only here.
__device__ float g_cH[32 * 32], g_sH[32 * 32];
__device__ float g_cL[32 * 64], g_sL[32 * 64];

// ---------------------------------------------------------------------------
// Stage A: 3072 double-trig anchors. Stage B: float combine (exact angle add).
// ---------------------------------------------------------------------------
__global__ void rope_anchors()
{
    const int idx = blockIdx.x * blockDim.x + threadIdx.x;
    if (idx >= 32 * 96) return;
    const int p = idx & 31;
    const int j = idx >> 5;          // 0..95
    const double invf = pow(10000.0, -((double)(2 * p)) / 64.0);
    if (j < 32) {
        const double ang = (double)(j * 64) * invf;
        g_cH[p * 32 + j] = (float)cos(ang);
        g_sH[p * 32 + j] = (float)sin(ang);
    } else {
        const int lo = j - 32;       // 0..63
        const double ang = (double)lo * invf;
        g_cL[p * 64 + lo] = (float)cos(ang);
        g_sL[p * 64 + lo] = (float)sin(ang);
    }
}

__global__ void rope_combine()
{
    const int idx = blockIdx.x * blockDim.x + threadIdx.x;
    if (idx >= SEQ * 32) return;
    const int p = idx & 31;
    const int s = idx >> 5;
    const int hi = s >> 6, lo = s & 63;
    const float cH = g_cH[p * 32 + hi], sH = g_sH[p * 32 + hi];
    const float cL = g_cL[p * 64 + lo], sL = g_sL[p * 64 + lo];
    g_cos[idx] = cH * cL - sH * sL;
    g_sin[idx] = sH * cL + cH * sL;
}

// ---------------------------------------------------------------------------
__device__ __forceinline__ void mma16n8k16h(float* d, const uint32_t* a,
                                            const uint32_t* b) {
    asm("mma.sync.aligned.m16n8k16.row.col.f32.f16.f16.f32 "
        "{%0,%1,%2,%3}, {%4,%5,%6,%7}, {%8,%9}, {%0,%1,%2,%3};"
        : "+f"(d[0]), "+f"(d[1]), "+f"(d[2]), "+f"(d[3])
        : "r"(a[0]), "r"(a[1]), "r"(a[2]), "r"(a[3]),
          "r"(b[0]), "r"(b[1]));
}

#define LDMX4(r0, r1, r2, r3, addr) \
    asm volatile("ldmatrix.sync.aligned.m8n8.x4.shared.b16 {%0,%1,%2,%3}, [%4];" \
                 : "=r"(r0), "=r"(r1), "=r"(r2), "=r"(r3) : "r"(addr))

#define CP_ASYNC16(dst_u32, src_ptr) \
    asm volatile("cp.async.ca.shared.global [%0], [%1], 16;" \
                 :: "r"(dst_u32), "l"(src_ptr))
#define CP_COMMIT() asm volatile("cp.async.commit_group;")
#define CP_WAIT(n)  asm volatile("cp.async.wait_group %0;" :: "n"(n))

// ---------------------------------------------------------------------------
// Prep kernels (validated R14/R15)
// ---------------------------------------------------------------------------
__global__ void conv_hs(const float* __restrict__ in, __half* __restrict__ outp)
{
    const int i = blockIdx.x * 256 + threadIdx.x;
    float4 v = ((const float4*)in)[i];
    __half2 h0 = __floats2half2_rn(v.x, v.y);
    __half2 h1 = __floats2half2_rn(v.z, v.w);
    uint2 u;
    u.x = *(uint32_t*)&h0; u.y = *(uint32_t*)&h1;
    *(uint2*)(outp + (size_t)i * 4) = u;
}

__global__ void transpose_w_h(const float* __restrict__ Wq,
                              const float* __restrict__ Wk,
                              const float* __restrict__ Wv,
                              const float* __restrict__ Wo)
{
    const int z = blockIdx.z;
    const float* W; __half* T; int N;
    if (z == 0)      { W = Wq; T = g_wth + WT_Q; N = 1024; }
    else if (z == 1) { W = Wk; T = g_wth + WT_K; N = 512; }
    else if (z == 2) { W = Wv; T = g_wth + WT_V; N = 512; }
    else             { W = Wo; T = g_wth + WT_O; N = 1024; }
    if (blockIdx.x * 32 >= N) return;

    __shared__ float t[32][33];
    const int n0 = blockIdx.x * 32, k0 = blockIdx.y * 32;
    const int tx = threadIdx.x & 31, ty = threadIdx.x >> 5;
#pragma unroll
    for (int r = 0; r < 4; r++)
        t[ty + r * 8][tx] = W[(size_t)(k0 + ty + r * 8) * N + n0 + tx];
    __syncthreads();
#pragma unroll
    for (int r = 0; r < 4; r++)
        T[(size_t)(n0 + ty + r * 8) * 1024 + k0 + tx] = __float2half(t[tx][ty + r * 8]);
}

// ---------------------------------------------------------------------------
// fp16 tensor-core GEMM, 3-stage cp.async ring (validated R16) with
// ldmatrix.x4 fragment loads (6 ldmatrix vs 24 LDS.32 per k16-step).
// C = A[M,K]h @ W, BT = W^T [N,K]h. BM=BN=128, BK=32, 256 thr, warp 64x32.
// Smem rows stride 40 halves (80 B) -> ldmatrix rows hit disjoint bank quads.
// ---------------------------------------------------------------------------
#define GEMM_SMEM_BYTES (3 * 2 * 128 * 40 * 2)
#define STG_BYTES (128 * 40 * 2)   // 10240 per stage per operand

template <int MODE>
__device__ __forceinline__ void gemm_body(
    const __half* __restrict__ A, const __half* __restrict__ BT,
    void* __restrict__ C, int N, int NH)
{
    extern __shared__ __half hsm[];
    const uint32_t Abase = (uint32_t)__cvta_generic_to_shared(hsm);
    const uint32_t Bbase = Abase + 3 * STG_BYTES;

    const int K = DM;
    const int tid  = threadIdx.x;
    const int lane = tid & 31;
    const int wid  = tid >> 5;
    const int wy   = wid >> 2;
    const int wx   = wid & 3;
    const int r4   = lane >> 2;
    const int c4   = lane & 3;
    const int m0   = blockIdx.y * 128, n0 = blockIdx.x * 128;

    const __half* Ab = A + (size_t)m0 * K;
    const __half* Bb = BT + (size_t)n0 * K;

    // ldmatrix per-lane offsets (bytes within a stage's operand block)
    // A: lanes 0-15 -> rows 0-15 @ k0; lanes 16-31 -> rows 0-15 @ k+8 halves
    const uint32_t a_lane = (uint32_t)((lane & 15) * 80 + (lane >> 4) * 16);
    // B: lane group (l>>4) selects n+8; (l>>3)&1 selects k+8
    const uint32_t b_lane = (uint32_t)(((lane >> 4) * 8 + (lane & 7)) * 80 +
                                       ((lane >> 3) & 1) * 16);

#define GF_FILL(st, kt) do {                                                  \
    _Pragma("unroll")                                                         \
    for (int i0 = 0; i0 < 2; i0++) {                                          \
        const int i = tid + i0 * 256;                                         \
        const int r = i >> 2, c = (i & 3) * 8;                                \
        CP_ASYNC16(Abase + (st) * STG_BYTES + (uint32_t)(r * 80 + c * 2),     \
                   Ab + (size_t)r * K + (kt) * 32 + c);                       \
        CP_ASYNC16(Bbase + (st) * STG_BYTES + (uint32_t)(r * 80 + c * 2),     \
                   Bb + (size_t)r * K + (kt) * 32 + c);                       \
    }                                                                         \
    CP_COMMIT();                                                              \
} while (0)

    const int NT = K / 32;   // 32
    GF_FILL(0, 0);
    GF_FILL(1, 1);

    float acc[4][4][4] = {};

    for (int kt = 0; kt < NT; kt++) {
        const int st = kt % 3;
        if (kt + 1 < NT) { CP_WAIT(1); } else { CP_WAIT(0); }
        __syncthreads();

        const uint32_t Ast = Abase + st * STG_BYTES + a_lane;
        const uint32_t Bst = Bbase + st * STG_BYTES + b_lane;

#pragma unroll
        for (int ks2 = 0; ks2 < 2; ks2++) {
            uint32_t af[4][4], bf[4][2];
#pragma unroll
            for (int mt = 0; mt < 4; mt++) {
                const uint32_t aa = Ast + (uint32_t)((wy * 64 + mt * 16) * 80 + ks2 * 32);
                LDMX4(af[mt][0], af[mt][1], af[mt][2], af[mt][3], aa);
            }
#pragma unroll
            for (int nt2 = 0; nt2 < 2; nt2++) {
                const uint32_t ba = Bst + (uint32_t)((wx * 32 + nt2 * 16) * 80 + ks2 * 32);
                LDMX4(bf[2 * nt2][0], bf[2 * nt2][1],
                      bf[2 * nt2 + 1][0], bf[2 * nt2 + 1][1], ba);
            }
#pragma unroll
            for (int mt = 0; mt < 4; mt++)
#pragma unroll
                for (int nt = 0; nt < 4; nt++)
                    mma16n8k16h(acc[mt][nt], af[mt], bf[nt]);
        }

        if (kt + 2 < NT) GF_FILL((kt + 2) % 3, kt + 2);
    }
#undef GF_FILL

#pragma unroll
    for (int mt = 0; mt < 4; mt++) {
#pragma unroll
        for (int nt = 0; nt < 4; nt++) {
            const int m = m0 + wy * 64 + mt * 16 + r4;
            const int n = n0 + wx * 32 + nt * 8 + 2 * c4;
#pragma unroll
            for (int half_ = 0; half_ < 2; half_++) {
                const int mr = m + half_ * 8;
                const float v0 = acc[mt][nt][half_ * 2];
                const float v1 = acc[mt][nt][half_ * 2 + 1];
                if (MODE == 0) {
                    *(float2*)((float*)C + (size_t)mr * DM + n) =
                        make_float2(v0, v1);
                } else {
                    const int b = mr / SEQ, s = mr % SEQ;
                    const int h = n >> 6, d = n & 63;
                    *(__half2*)((__half*)C +
                        (((size_t)(b * NH + h)) * SEQ + s) * HDIM + d) =
                        __floats2half2_rn(v0, v1);
                }
            }
        }
    }
}

__global__ void __launch_bounds__(256, 2)
gemm_qkv(const __half* __restrict__ hsh)
{
    const int z = blockIdx.z;
    const __half* BT; __half* C; int N, NH;
    if (z == 0)      { BT = g_wth + WT_Q; C = g_q; N = 1024; NH = HN;  }
    else if (z == 1) { BT = g_wth + WT_K; C = g_k; N = 512;  NH = KVN; }
    else             { BT = g_wth + WT_V; C = g_v; N = 512;  NH = KVN; }
    if (blockIdx.x * 128 >= N) return;
    gemm_body<1>(hsh, BT, C, N, NH);
}

__global__ void __launch_bounds__(256, 2)
gemm_out(float* __restrict__ out)
{
    gemm_body<0>(g_attn, g_wth + WT_O, out, 1024, 0);
}

// ---------------------------------------------------------------------------
// fp16 MMA flash attention (validated R15/R16 — frozen): 128 thr = 4 warps,
// 64-q tile, fused RoPE staging, V staged transposed, all MMAs m16n8k16.
// ---------------------------------------------------------------------------
#define AHS 72

__global__ void __launch_bounds__(128) attn_mma()
{
    __shared__ __half Ps[64][AHS];
    __shared__ __half Ks[64][AHS];
    __shared__ __half Vt[64][AHS];

    const int b = blockIdx.z, h = blockIdx.y;
    const int qb = blockIdx.x * 64;
    const int kvh = h >> 1;
    const int tid  = threadIdx.x;
    const int lane = tid & 31;
    const int wid  = tid >> 5;
    const int mb   = wid * 16;
    const int r4   = lane >> 2;
    const int c4   = lane & 3;

    const __half* qg = g_q + ((size_t)(b * HN + h) * SEQ + qb) * HDIM;
    const __half* kg = g_k + (size_t)(b * KVN + kvh) * SEQ * HDIM;
    const __half* vg = g_v + (size_t)(b * KVN + kvh) * SEQ * HDIM;

    for (int i = tid; i < 64 * 8; i += 128) {
        const int row = i >> 3;
        const int col = (i & 7) * 4;
        uint2 u1 = *(const uint2*)(qg + row * HDIM + col);
        uint2 u2 = *(const uint2*)(qg + row * HDIM + col + 32);
        float2 a0 = __half22float2(*(__half2*)&u1.x);
        float2 a1 = __half22float2(*(__half2*)&u1.y);
        float2 b0 = __half22float2(*(__half2*)&u2.x);
        float2 b1 = __half22float2(*(__half2*)&u2.y);
        const float4 cc = *(const float4*)(&g_cos[(qb + row) * 32 + col]);
        const float4 ss = *(const float4*)(&g_sin[(qb + row) * 32 + col]);
        *(__half2*)&Ps[row][col] = __floats2half2_rn(
            (a0.x * cc.x - b0.x * ss.x) * 0.125f,
            (a0.y * cc.y - b0.y * ss.y) * 0.125f);
        *(__half2*)&Ps[row][col + 2] = __floats2half2_rn(
            (a1.x * cc.z - b1.x * ss.z) * 0.125f,
            (a1.y * cc.w - b1.y * ss.w) * 0.125f);
        *(__half2*)&Ps[row][col + 32] = __floats2half2_rn(
            (b0.x * cc.x + a0.x * ss.x) * 0.125f,
            (b0.y * cc.y + a0.y * ss.y) * 0.125f);
        *(__half2*)&Ps[row][col + 34] = __floats2half2_rn(
            (b1.x * cc.z + a1.x * ss.z) * 0.125f,
            (b1.y * cc.w + a1.y * ss.w) * 0.125f);
    }
    __syncthreads();

    uint32_t aq[4][4];
#pragma unroll
    for (int ks = 0; ks < 4; ks++) {
        const uint32_t* r0 = (const uint32_t*)&Ps[mb + r4][0];
        const uint32_t* r1 = (const uint32_t*)&Ps[mb + r4 + 8][0];
        aq[ks][0] = r0[ks * 8 + c4];
        aq[ks][1] = r1[ks * 8 + c4];
        aq[ks][2] = r0[ks * 8 + c4 + 4];
        aq[ks][3] = r1[ks * 8 + c4 + 4];
    }

    float oacc[8][4] = {};
    float m2[2] = {-1e30f, -1e30f};
    float l2[2] = {0.0f, 0.0f};
    const int qi0 = qb + mb + r4;
    const int qi1 = qi0 + 8;

    const int kstart = (qb >= WIN) ? (qb - WIN) : 0;

    for (int kb = kstart; kb <= qb; kb += 64) {
        __syncthreads();
        for (int i = tid; i < 64 * 8; i += 128) {
            const int row = i >> 3;
            const int col = (i & 7) * 4;
            uint2 u1 = *(const uint2*)(kg + (size_t)(kb + row) * HDIM + col);
            uint2 u2 = *(const uint2*)(kg + (size_t)(kb + row) * HDIM + col + 32);
            float2 a0 = __half22float2(*(__half2*)&u1.x);
            float2 a1 = __half22float2(*(__half2*)&u1.y);
            float2 b0 = __half22float2(*(__half2*)&u2.x);
            float2 b1 = __half22float2(*(__half2*)&u2.y);
            const float4 cc = *(const float4*)(&g_cos[(kb + row) * 32 + col]);
            const float4 ss = *(const float4*)(&g_sin[(kb + row) * 32 + col]);
            *(__half2*)&Ks[row][col] = __floats2half2_rn(
                a0.x * cc.x - b0.x * ss.x, a0.y * cc.y - b0.y * ss.y);
            *(__half2*)&Ks[row][col + 2] = __floats2half2_rn(
                a1.x * cc.z - b1.x * ss.z, a1.y * cc.w - b1.y * ss.w);
            *(__half2*)&Ks[row][col + 32] = __floats2half2_rn(
                b0.x * cc.x + a0.x * ss.x, b0.y * cc.y + a0.y * ss.y);
            *(__half2*)&Ks[row][col + 34] = __floats2half2_rn(
                b1.x * cc.z + a1.x * ss.z, b1.y * cc.w + a1.y * ss.w);
        }
        for (int i = tid; i < 32 * 8; i += 128) {
            const int kp = i & 31;
            const int dg = i >> 5;
            const __half* v0 = vg + (size_t)(kb + 2 * kp) * HDIM + dg * 8;
            const __half* v1 = v0 + HDIM;
            uint4 ua = *(const uint4*)v0;
            uint4 ub = *(const uint4*)v1;
            const __half* ah = (const __half*)&ua;
            const __half* bh = (const __half*)&ub;
#pragma unroll
            for (int j = 0; j < 8; j++)
                *(__half2*)&Vt[dg * 8 + j][2 * kp] = __halves2half2(ah[j], bh[j]);
        }
        __syncthreads();

        float sacc[8][4] = {};
#pragma unroll
        for (int ks = 0; ks < 4; ks++) {
#pragma unroll
            for (int nt = 0; nt < 8; nt++) {
                const uint32_t* rn = (const uint32_t*)&Ks[nt * 8 + r4][0];
                uint32_t bk[2];
                bk[0] = rn[ks * 8 + c4];
                bk[1] = rn[ks * 8 + c4 + 4];
                mma16n8k16h(sacc[nt], aq[ks], bk);
            }
        }

        float rmax0 = -1e30f, rmax1 = -1e30f;
#pragma unroll
        for (int nt = 0; nt < 8; nt++) {
            const int kj = kb + nt * 8 + 2 * c4;
            if (!((kj     <= qi0) && (kj     + WIN >= qi0))) sacc[nt][0] = -1e30f;
            if (!((kj + 1 <= qi0) && (kj + 1 + WIN >= qi0))) sacc[nt][1] = -1e30f;
            if (!((kj     <= qi1) && (kj     + WIN >= qi1))) sacc[nt][2] = -1e30f;
            if (!((kj + 1 <= qi1) && (kj + 1 + WIN >= qi1))) sacc[nt][3] = -1e30f;
            rmax0 = fmaxf(rmax0, fmaxf(sacc[nt][0], sacc[nt][1]));
            rmax1 = fmaxf(rmax1, fmaxf(sacc[nt][2], sacc[nt][3]));
        }
        rmax0 = fmaxf(rmax0, __shfl_xor_sync(0xffffffffu, rmax0, 1));
        rmax0 = fmaxf(rmax0, __shfl_xor_sync(0xffffffffu, rmax0, 2));
        rmax1 = fmaxf(rmax1, __shfl_xor_sync(0xffffffffu, rmax1, 1));
        rmax1 = fmaxf(rmax1, __shfl_xor_sync(0xffffffffu, rmax1, 2));

        const float mn0 = fmaxf(m2[0], rmax0);
        const float mn1 = fmaxf(m2[1], rmax1);
        const float al0 = __expf(m2[0] - mn0);
        const float al1 = __expf(m2[1] - mn1);
        m2[0] = mn0; m2[1] = mn1;

        float rs0 = 0.f, rs1 = 0.f;
#pragma unroll
        for (int nt = 0; nt < 8; nt++) {
            const float p0 = (sacc[nt][0] > -1e29f) ? __expf(sacc[nt][0] - mn0) : 0.f;
            const float p1 = (sacc[nt][1] > -1e29f) ? __expf(sacc[nt][1] - mn0) : 0.f;
            const float p2 = (sacc[nt][2] > -1e29f) ? __expf(sacc[nt][2] - mn1) : 0.f;
            const float p3 = (sacc[nt][3] > -1e29f) ? __expf(sacc[nt][3] - mn1) : 0.f;
            rs0 += p0 + p1; rs1 += p2 + p3;
            *(__half2*)&Ps[mb + r4    ][nt * 8 + 2 * c4] = __floats2half2_rn(p0, p1);
            *(__half2*)&Ps[mb + r4 + 8][nt * 8 + 2 * c4] = __floats2half2_rn(p2, p3);
        }
        rs0 += __shfl_xor_sync(0xffffffffu, rs0, 1);
        rs0 += __shfl_xor_sync(0xffffffffu, rs0, 2);
        rs1 += __shfl_xor_sync(0xffffffffu, rs1, 1);
        rs1 += __shfl_xor_sync(0xffffffffu, rs1, 2);
        l2[0] = l2[0] * al0 + rs0;
        l2[1] = l2[1] * al1 + rs1;

#pragma unroll
        for (int dt = 0; dt < 8; dt++) {
            oacc[dt][0] *= al0; oacc[dt][1] *= al0;
            oacc[dt][2] *= al1; oacc[dt][3] *= al1;
        }
        __syncwarp();

#pragma unroll
        for (int ks = 0; ks < 4; ks++) {
            const uint32_t* p0 = (const uint32_t*)&Ps[mb + r4][0];
            const uint32_t* p1 = (const uint32_t*)&Ps[mb + r4 + 8][0];
            uint32_t ap[4];
            ap[0] = p0[ks * 8 + c4];
            ap[1] = p1[ks * 8 + c4];
            ap[2] = p0[ks * 8 + c4 + 4];
            ap[3] = p1[ks * 8 + c4 + 4];
#pragma unroll
            for (int dt = 0; dt < 8; dt++) {
                const uint32_t* rv = (const uint32_t*)&Vt[dt * 8 + r4][0];
                uint32_t bv[2];
                bv[0] = rv[ks * 8 + c4];
                bv[1] = rv[ks * 8 + c4 + 4];
                mma16n8k16h(oacc[dt], ap, bv);
            }
        }
    }

    const float inv0 = 1.0f / l2[0];
    const float inv1 = 1.0f / l2[1];
#pragma unroll
    for (int dt = 0; dt < 8; dt++) {
        const int d = dt * 8 + 2 * c4;
        __half* o0 = g_attn + ((size_t)(b * SEQ + qi0) * HN + h) * HDIM + d;
        __half* o1 = g_attn + ((size_t)(b * SEQ + qi1) * HN + h) * HDIM + d;
        *(__half2*)o0 = __floats2half2_rn(oacc[dt][0] * inv0, oacc[dt][1] * inv0);
        *(__half2*)o1 = __floats2half2_rn(oacc[dt][2] * inv1, oacc[dt][3] * inv1);
    }
}

// ---------------------------------------------------------------------------
extern "C" void kernel_launch(void* const* d_in, const int* in_sizes, int n_in,
                              void* d_out, int out_size)
{
    const float* hs = (const float*)d_in[0];
    const float* Wq = (const float*)d_in[1];
    const float* Wk = (const float*)d_in[2];
    const float* Wv = (const float*)d_in[3];
    const float* Wo = (const float*)d_in[4];
    float* out = (float*)d_out;

    __half* hsh;
    cudaGetSymbolAddress((void**)&hsh, g_hsh);

    // RoPE table: double-trig anchors (3072) + float combine (65536)
    rope_anchors<<<(32 * 96 + 255) / 256, 256>>>();
    rope_combine<<<(SEQ * 32) / 256, 256>>>();

    // Prep: half operands
    conv_hs<<<(BATCH * SEQ * DM / 4) / 256, 256>>>(hs, hsh);
    transpose_w_h<<<dim3(32, 32, 4), 256>>>(Wq, Wk, Wv, Wo);

    cudaFuncSetAttribute(gemm_qkv,
                         cudaFuncAttributeMaxDynamicSharedMemorySize,
                         GEMM_SMEM_BYTES);
    cudaFuncSetAttribute(gemm_out,
                         cudaFuncAttributeMaxDynamicSharedMemorySize,
                         GEMM_SMEM_BYTES);

    // QKV projections (fp16 MMA, 3-stage pipeline, ldmatrix fragments)
    gemm_qkv<<<dim3(1024 / 128, (BATCH * SEQ) / 128, 3), 256,
               GEMM_SMEM_BYTES>>>(hsh);

    // Attention (fp16 MMA flash, fused RoPE)
    attn_mma<<<dim3(SEQ / 64, HN, BATCH), 128>>>();

    // Output projection (fp16 MMA, float output)
    gemm_out<<<dim3(1024 / 128, (BATCH * SEQ) / 128), 256,
               GEMM_SMEM_BYTES>>>(out);
}